// round 3
// baseline (speedup 1.0000x reference)
#include <cuda_runtime.h>
#include <math.h>

#define BATCH 4
#define NPTS 20000
#define NS 1024
#define NC 128
#define NK 32
#define NREF (BATCH * NS)   // 4096

// ---------------- scratch (static device globals; no allocations) ----------------
__device__ int   g_idx[NREF * NK];                         // 512 KB
__device__ float g_x2[(size_t)NREF * NK * 128];            // 64 MiB

// =====================================================================
// Kernel 1: ball query. One warp per ref point, early exit at K hits.
// Matches reference semantics: first K in-ball indices in ascending
// index order; pad with first hit; empty ball -> N-1.
// Distance formula matches reference: |r|^2 + |p|^2 - 2 r.p  (fp32).
// =====================================================================
__global__ __launch_bounds__(256) void ball_query_kernel(
    const float* __restrict__ points, const float* __restrict__ refs)
{
    int warp = (blockIdx.x * 256 + threadIdx.x) >> 5;
    int lane = threadIdx.x & 31;
    if (warp >= NREF) return;
    int b = warp >> 10;
    const float* rp = refs + (size_t)warp * 3;
    float rx = rp[0], ry = rp[1], rz = rp[2];
    float rr2 = rx * rx + ry * ry + rz * rz;
    const float R2 = 0.2f * 0.2f;
    int* out = g_idx + warp * NK;
    const float* pbase = points + (size_t)b * NPTS * 3;

    int count = 0;
    int first = -1;
    for (int base = 0; base < NPTS && count < NK; base += 32) {
        int i = base + lane;                      // NPTS % 32 == 0 (20000 = 625*32)
        float px = pbase[i * 3 + 0];
        float py = pbase[i * 3 + 1];
        float pz = pbase[i * 3 + 2];
        float pp2 = px * px + py * py + pz * pz;
        float dot = rx * px + ry * py + rz * pz;
        float d2 = rr2 + pp2 - 2.0f * dot;
        bool pred = d2 < R2;
        unsigned m = __ballot_sync(0xffffffffu, pred);
        if (m) {
            if (first < 0) first = __shfl_sync(0xffffffffu, i, __ffs(m) - 1);
            if (pred) {
                int rank = __popc(m & ((1u << lane) - 1u));
                int slot = count + rank;
                if (slot < NK) out[slot] = i;
            }
            count += __popc(m);
        }
    }
    if (count < NK) {
        int fill = (count == 0) ? (NPTS - 1) : first;
        if (lane >= count) out[lane] = fill;      // NK == 32 == warp size
    }
}

// =====================================================================
// Kernel 2: gather + layer1 (131->64) + layer2 (64->128), BN+ReLU folded.
// One block = 4 refs = 128 rows. Weights staged in smem. x2 -> global scratch.
// =====================================================================
#define X0_STRIDE 133   // 131 cols + pad; 8*133 mod 32 != 0 (broadcast-friendly)
#define X1_STRIDE 69    // 64 cols + pad

// smem layout (floats)
#define SM2_W1   0                    // 131*64 = 8384
#define SM2_W2   (SM2_W1 + 131*64)    // 64*128 = 8192
#define SM2_X0   (SM2_W2 + 64*128)    // 128*133 = 17024
#define SM2_X1   (SM2_X0 + 128*X0_STRIDE)  // 128*69 = 8832
#define SM2_SC1  (SM2_X1 + 128*X1_STRIDE)  // 64
#define SM2_SH1  (SM2_SC1 + 64)
#define SM2_SC2  (SM2_SH1 + 64)       // 128
#define SM2_SH2  (SM2_SC2 + 128)
#define SM2_REFC (SM2_SH2 + 128)      // 12
#define SM2_TOTAL ((SM2_REFC + 16) * 4)

__global__ __launch_bounds__(256) void mlp12_kernel(
    const float* __restrict__ points, const float* __restrict__ features,
    const float* __restrict__ refs,
    const float* __restrict__ W1, const float* __restrict__ g1,
    const float* __restrict__ b1, const float* __restrict__ m1,
    const float* __restrict__ v1,
    const float* __restrict__ W2, const float* __restrict__ g2,
    const float* __restrict__ b2, const float* __restrict__ m2,
    const float* __restrict__ v2)
{
    extern __shared__ float sm[];
    float* W1s = sm + SM2_W1;
    float* W2s = sm + SM2_W2;
    float* x0  = sm + SM2_X0;
    float* x1  = sm + SM2_X1;
    float* sc1 = sm + SM2_SC1;
    float* sh1 = sm + SM2_SH1;
    float* sc2 = sm + SM2_SC2;
    float* sh2 = sm + SM2_SH2;
    float* refc = sm + SM2_REFC;

    int t = threadIdx.x;
    int g = blockIdx.x;          // group of 4 refs
    int ref0 = g * 4;
    int b = ref0 >> 10;

    for (int e = t; e < 131 * 64; e += 256) W1s[e] = W1[e];
    for (int e = t; e < 64 * 128; e += 256) W2s[e] = W2[e];
    if (t < 64) {
        float s = g1[t] * rsqrtf(v1[t] + 1e-5f);
        sc1[t] = s; sh1[t] = b1[t] - m1[t] * s;
    } else if (t < 192) {
        int j = t - 64;
        float s = g2[j] * rsqrtf(v2[j] + 1e-5f);
        sc2[j] = s; sh2[j] = b2[j] - m2[j] * s;
    }
    if (t < 12) refc[t] = refs[(size_t)ref0 * 3 + t];
    __syncthreads();

    // ---- gather: x0[row 0..127][col 0..130] ----
    const int E = 128 * 131;
    for (int e = t; e < E; e += 256) {
        int rr = e / 131;
        int c = e - rr * 131;
        int q = rr >> 5, kk = rr & 31;
        int pid = g_idx[(ref0 + q) * NK + kk];
        float val;
        if (c < 3) {
            val = (points[((size_t)b * NPTS + pid) * 3 + c] - refc[q * 3 + c]) * 5.0f;
        } else {
            val = features[((size_t)b * NPTS + pid) * 128 + (c - 3)];
        }
        x0[rr * X0_STRIDE + c] = val;
    }
    __syncthreads();

    int ty = t >> 4;     // 0..15 -> 8 rows each
    int tx = t & 15;
    int r0 = ty * 8;

    // ---- layer1: 128x64, microtile 8 rows x 4 cols ----
    {
        int c0 = tx * 4;
        float acc[8][4];
        #pragma unroll
        for (int i = 0; i < 8; i++)
            #pragma unroll
            for (int j = 0; j < 4; j++) acc[i][j] = 0.0f;

        const float* x0r = x0 + r0 * X0_STRIDE;
        for (int k = 0; k < 131; k++) {
            float4 w = *(const float4*)(W1s + k * 64 + c0);
            #pragma unroll
            for (int i = 0; i < 8; i++) {
                float a = x0r[i * X0_STRIDE + k];
                acc[i][0] = fmaf(a, w.x, acc[i][0]);
                acc[i][1] = fmaf(a, w.y, acc[i][1]);
                acc[i][2] = fmaf(a, w.z, acc[i][2]);
                acc[i][3] = fmaf(a, w.w, acc[i][3]);
            }
        }
        #pragma unroll
        for (int j = 0; j < 4; j++) {
            float s = sc1[c0 + j], h = sh1[c0 + j];
            #pragma unroll
            for (int i = 0; i < 8; i++) {
                float y = fmaxf(fmaf(acc[i][j], s, h), 0.0f);
                x1[(r0 + i) * X1_STRIDE + c0 + j] = y;
            }
        }
    }
    __syncthreads();

    // ---- layer2: 128x128, microtile 8x8 ----
    {
        int c0 = tx * 8;
        float acc[8][8];
        #pragma unroll
        for (int i = 0; i < 8; i++)
            #pragma unroll
            for (int j = 0; j < 8; j++) acc[i][j] = 0.0f;

        const float* x1r = x1 + r0 * X1_STRIDE;
        for (int k = 0; k < 64; k++) {
            float4 w0 = *(const float4*)(W2s + k * 128 + c0);
            float4 w1 = *(const float4*)(W2s + k * 128 + c0 + 4);
            #pragma unroll
            for (int i = 0; i < 8; i++) {
                float a = x1r[i * X1_STRIDE + k];
                acc[i][0] = fmaf(a, w0.x, acc[i][0]);
                acc[i][1] = fmaf(a, w0.y, acc[i][1]);
                acc[i][2] = fmaf(a, w0.z, acc[i][2]);
                acc[i][3] = fmaf(a, w0.w, acc[i][3]);
                acc[i][4] = fmaf(a, w1.x, acc[i][4]);
                acc[i][5] = fmaf(a, w1.y, acc[i][5]);
                acc[i][6] = fmaf(a, w1.z, acc[i][6]);
                acc[i][7] = fmaf(a, w1.w, acc[i][7]);
            }
        }
        #pragma unroll
        for (int i = 0; i < 8; i++) {
            size_t row = (size_t)g * 128 + r0 + i;
            float o[8];
            #pragma unroll
            for (int j = 0; j < 8; j++)
                o[j] = fmaxf(fmaf(acc[i][j], sc2[c0 + j], sh2[c0 + j]), 0.0f);
            float4 v0 = make_float4(o[0], o[1], o[2], o[3]);
            float4 v1v = make_float4(o[4], o[5], o[6], o[7]);
            *(float4*)&g_x2[row * 128 + c0] = v0;
            *(float4*)&g_x2[row * 128 + c0 + 4] = v1v;
        }
    }
}

// =====================================================================
// Kernel 3: layer3 (128->256) + BN + ReLU + max over K=32 rows.
// Block tile: 128 rows (= 4 refs) x 128 cols. grid = (1024, 2).
// =====================================================================
#define AS_STRIDE 133
#define WS_STRIDE 132

#define SM3_A   0                           // 128*133 = 17024
#define SM3_W   (SM3_A + 128*AS_STRIDE)     // 128*132 = 16896
#define SM3_RED (SM3_W + 128*WS_STRIDE)     // 16*128 = 2048
#define SM3_SC  (SM3_RED + 16*128)          // 128
#define SM3_SH  (SM3_SC + 128)              // 128
#define SM3_TOTAL ((SM3_SH + 128) * 4)

__global__ __launch_bounds__(256) void mlp3_kernel(
    const float* __restrict__ W3, const float* __restrict__ g3,
    const float* __restrict__ b3, const float* __restrict__ m3,
    const float* __restrict__ v3, float* __restrict__ out)
{
    extern __shared__ float sm[];
    float* As  = sm + SM3_A;
    float* Ws  = sm + SM3_W;
    float* red = sm + SM3_RED;
    float* sc3 = sm + SM3_SC;
    float* sh3 = sm + SM3_SH;

    int t = threadIdx.x;
    int g = blockIdx.x;          // row group: rows [g*128, g*128+128)
    int colbase = blockIdx.y * 128;

    // load A tile [128 rows][128 k], row-major, padded stride
    for (int e4 = t; e4 < 128 * 32; e4 += 256) {
        int row = e4 >> 5;
        int k4 = (e4 & 31) << 2;
        float4 v = *(const float4*)&g_x2[((size_t)g * 128 + row) * 128 + k4];
        float* dst = As + row * AS_STRIDE + k4;
        dst[0] = v.x; dst[1] = v.y; dst[2] = v.z; dst[3] = v.w;
    }
    // load W tile [128 k][128 cols]
    for (int e4 = t; e4 < 128 * 32; e4 += 256) {
        int k = e4 >> 5;
        int c4 = (e4 & 31) << 2;
        float4 v = *(const float4*)&W3[k * 256 + colbase + c4];
        *(float4*)&Ws[k * WS_STRIDE + c4] = v;
    }
    if (t < 128) {
        int j = colbase + t;
        float s = g3[j] * rsqrtf(v3[j] + 1e-5f);
        sc3[t] = s; sh3[t] = b3[j] - m3[j] * s;
    }
    __syncthreads();

    int ty = t >> 4;     // 0..15 -> rows 8*ty..8*ty+7 (always within one ref's 32 rows)
    int tx = t & 15;     // cols 8*tx..8*tx+7
    int r0 = ty * 8;
    int c0 = tx * 8;

    float acc[8][8];
    #pragma unroll
    for (int i = 0; i < 8; i++)
        #pragma unroll
        for (int j = 0; j < 8; j++) acc[i][j] = 0.0f;

    const float* Ar = As + r0 * AS_STRIDE;
    for (int k = 0; k < 128; k++) {
        float4 w0 = *(const float4*)(Ws + k * WS_STRIDE + c0);
        float4 w1 = *(const float4*)(Ws + k * WS_STRIDE + c0 + 4);
        #pragma unroll
        for (int i = 0; i < 8; i++) {
            float a = Ar[i * AS_STRIDE + k];
            acc[i][0] = fmaf(a, w0.x, acc[i][0]);
            acc[i][1] = fmaf(a, w0.y, acc[i][1]);
            acc[i][2] = fmaf(a, w0.z, acc[i][2]);
            acc[i][3] = fmaf(a, w0.w, acc[i][3]);
            acc[i][4] = fmaf(a, w1.x, acc[i][4]);
            acc[i][5] = fmaf(a, w1.y, acc[i][5]);
            acc[i][6] = fmaf(a, w1.z, acc[i][6]);
            acc[i][7] = fmaf(a, w1.w, acc[i][7]);
        }
    }

    // BN + ReLU + max over this thread's 8 rows (all within one ref)
    #pragma unroll
    for (int j = 0; j < 8; j++) {
        float s = sc3[c0 + j], h = sh3[c0 + j];
        float mx = 0.0f;   // ReLU => >= 0
        #pragma unroll
        for (int i = 0; i < 8; i++)
            mx = fmaxf(mx, fmaxf(fmaf(acc[i][j], s, h), 0.0f));
        red[ty * 128 + c0 + j] = mx;
    }
    __syncthreads();

    // combine 4 ty-groups per ref (rows 32 per ref), write output
    for (int o = t; o < 512; o += 256) {
        int q = o >> 7;          // ref within group (0..3)
        int col = o & 127;
        float v = red[(4 * q + 0) * 128 + col];
        v = fmaxf(v, red[(4 * q + 1) * 128 + col]);
        v = fmaxf(v, red[(4 * q + 2) * 128 + col]);
        v = fmaxf(v, red[(4 * q + 3) * 128 + col]);
        out[((size_t)g * 4 + q) * 256 + colbase + col] = v;
    }
}

// =====================================================================
extern "C" void kernel_launch(void* const* d_in, const int* in_sizes, int n_in,
                              void* d_out, int out_size)
{
    const float* points   = (const float*)d_in[0];
    const float* features = (const float*)d_in[1];
    const float* refs     = (const float*)d_in[2];
    const float* W1 = (const float*)d_in[3];
    const float* g1 = (const float*)d_in[4];
    const float* b1 = (const float*)d_in[5];
    const float* m1 = (const float*)d_in[6];
    const float* v1 = (const float*)d_in[7];
    const float* W2 = (const float*)d_in[8];
    const float* g2 = (const float*)d_in[9];
    const float* b2 = (const float*)d_in[10];
    const float* m2 = (const float*)d_in[11];
    const float* v2 = (const float*)d_in[12];
    const float* W3 = (const float*)d_in[13];
    const float* g3 = (const float*)d_in[14];
    const float* b3 = (const float*)d_in[15];
    const float* m3 = (const float*)d_in[16];
    const float* v3 = (const float*)d_in[17];
    float* out = (float*)d_out;

    cudaFuncSetAttribute(mlp12_kernel, cudaFuncAttributeMaxDynamicSharedMemorySize, SM2_TOTAL);
    cudaFuncSetAttribute(mlp3_kernel,  cudaFuncAttributeMaxDynamicSharedMemorySize, SM3_TOTAL);

    ball_query_kernel<<<NREF / 8, 256>>>(points, refs);
    mlp12_kernel<<<NREF / 4, 256, SM2_TOTAL>>>(points, features, refs,
                                               W1, g1, b1, m1, v1,
                                               W2, g2, b2, m2, v2);
    mlp3_kernel<<<dim3(NREF / 4, 2), 256, SM3_TOTAL>>>(W3, g3, b3, m3, v3, out);
}

// round 5
// speedup vs baseline: 1.2001x; 1.2001x over previous
#include <cuda_runtime.h>
#include <math.h>

#define BATCH 4
#define NPTS 20000
#define NS 1024
#define NC 128
#define NK 32
#define NREF (BATCH * NS)   // 4096

// ---------------- scratch (static device globals; no allocations) ----------------
__device__ int   g_idx[NREF * NK];                         // 512 KB
__device__ float g_x2[(size_t)NREF * NK * 128];            // 64 MiB

// ---------------- packed f32x2 helpers (Blackwell fp32 2x FMA) ----------------
__device__ __forceinline__ unsigned long long dup_f32(float a) {
    unsigned long long r;
    asm("mov.b64 %0, {%1, %1};" : "=l"(r) : "r"(__float_as_uint(a)));
    return r;
}
__device__ __forceinline__ void fma2(unsigned long long& acc,
                                     unsigned long long a, unsigned long long w) {
    asm("fma.rn.f32x2 %0, %1, %2, %0;" : "+l"(acc) : "l"(a), "l"(w));
}
__device__ __forceinline__ float2 unpack_f32x2(unsigned long long v) {
    unsigned lo, hi;
    asm("mov.b64 {%0, %1}, %2;" : "=r"(lo), "=r"(hi) : "l"(v));
    return make_float2(__uint_as_float(lo), __uint_as_float(hi));
}

// =====================================================================
// Kernel 1: ball query. One warp per ref. 128 points per iteration with
// all loads batched (MLP~4) to shrink the latency-bound straggler path.
// Semantics identical to reference: first K in-ball indices ascending;
// pad with first hit; empty ball -> N-1. d2 = |r|^2+|p|^2-2 r.p (fp32).
// =====================================================================
__global__ __launch_bounds__(256) void ball_query_kernel(
    const float* __restrict__ points, const float* __restrict__ refs)
{
    int warp = (blockIdx.x * 256 + threadIdx.x) >> 5;
    int lane = threadIdx.x & 31;
    if (warp >= NREF) return;
    int b = warp >> 10;
    const float* rp = refs + (size_t)warp * 3;
    float rx = rp[0], ry = rp[1], rz = rp[2];
    float rr2 = rx * rx + ry * ry + rz * rz;
    const float R2 = 0.2f * 0.2f;
    int* out = g_idx + warp * NK;
    const float* pbase = points + (size_t)b * NPTS * 3;

    int count = 0;
    int first = -1;
    for (int base = 0; base < NPTS && count < NK; base += 128) {
        float px[4], py[4], pz[4];
        #pragma unroll
        for (int j = 0; j < 4; j++) {
            int i = base + j * 32 + lane;
            bool valid = (i < NPTS);
            int ii = valid ? i : 0;
            px[j] = pbase[ii * 3 + 0];
            py[j] = pbase[ii * 3 + 1];
            pz[j] = pbase[ii * 3 + 2];
            if (!valid) { px[j] = 1e9f; }   // forces d2 >= R2
        }
        #pragma unroll
        for (int j = 0; j < 4; j++) {
            int i = base + j * 32 + lane;
            float pp2 = px[j] * px[j] + py[j] * py[j] + pz[j] * pz[j];
            float dot = rx * px[j] + ry * py[j] + rz * pz[j];
            float d2 = rr2 + pp2 - 2.0f * dot;
            bool pred = d2 < R2;
            unsigned m = __ballot_sync(0xffffffffu, pred);
            if (m) {
                if (first < 0) first = __shfl_sync(0xffffffffu, i, __ffs(m) - 1);
                if (pred) {
                    int rank = __popc(m & ((1u << lane) - 1u));
                    int slot = count + rank;
                    if (slot < NK) out[slot] = i;
                }
                count += __popc(m);
            }
        }
    }
    if (count < NK) {
        int fill = (count == 0) ? (NPTS - 1) : first;
        if (lane >= count) out[lane] = fill;      // NK == 32 == warp size
    }
}

// =====================================================================
// Kernel 2: gather + layer1 (131->64) + layer2 (64->128), BN+ReLU folded.
// One block = 4 refs = 128 rows. f32x2 packed FMA in both GEMM loops.
// =====================================================================
#define X0_STRIDE 133   // 131 cols + pad
#define X1_STRIDE 69    // 64 cols + pad

// smem layout (floats)
#define SM2_W1   0                    // 131*64 = 8384
#define SM2_W2   (SM2_W1 + 131*64)    // 64*128 = 8192
#define SM2_X0   (SM2_W2 + 64*128)    // 128*133 = 17024
#define SM2_X1   (SM2_X0 + 128*X0_STRIDE)  // 128*69 = 8832
#define SM2_SC1  (SM2_X1 + 128*X1_STRIDE)  // 64
#define SM2_SH1  (SM2_SC1 + 64)
#define SM2_SC2  (SM2_SH1 + 64)       // 128
#define SM2_SH2  (SM2_SC2 + 128)
#define SM2_REFC (SM2_SH2 + 128)      // 12
#define SM2_TOTAL ((SM2_REFC + 16) * 4)

__global__ __launch_bounds__(256) void mlp12_kernel(
    const float* __restrict__ points, const float* __restrict__ features,
    const float* __restrict__ refs,
    const float* __restrict__ W1, const float* __restrict__ g1,
    const float* __restrict__ b1, const float* __restrict__ m1,
    const float* __restrict__ v1,
    const float* __restrict__ W2, const float* __restrict__ g2,
    const float* __restrict__ b2, const float* __restrict__ m2,
    const float* __restrict__ v2)
{
    extern __shared__ float sm[];
    float* W1s = sm + SM2_W1;
    float* W2s = sm + SM2_W2;
    float* x0  = sm + SM2_X0;
    float* x1  = sm + SM2_X1;
    float* sc1 = sm + SM2_SC1;
    float* sh1 = sm + SM2_SH1;
    float* sc2 = sm + SM2_SC2;
    float* sh2 = sm + SM2_SH2;
    float* refc = sm + SM2_REFC;

    int t = threadIdx.x;
    int g = blockIdx.x;          // group of 4 refs
    int ref0 = g * 4;
    int b = ref0 >> 10;

    for (int e = t; e < 131 * 64; e += 256) W1s[e] = W1[e];
    for (int e = t; e < 64 * 128; e += 256) W2s[e] = W2[e];
    if (t < 64) {
        float s = g1[t] * rsqrtf(v1[t] + 1e-5f);
        sc1[t] = s; sh1[t] = b1[t] - m1[t] * s;
    } else if (t < 192) {
        int j = t - 64;
        float s = g2[j] * rsqrtf(v2[j] + 1e-5f);
        sc2[j] = s; sh2[j] = b2[j] - m2[j] * s;
    }
    if (t < 12) refc[t] = refs[(size_t)ref0 * 3 + t];
    __syncthreads();

    // ---- gather: x0[row 0..127][col 0..130] ----
    const int E = 128 * 131;
    for (int e = t; e < E; e += 256) {
        int rr = e / 131;
        int c = e - rr * 131;
        int q = rr >> 5, kk = rr & 31;
        int pid = g_idx[(ref0 + q) * NK + kk];
        float val;
        if (c < 3) {
            val = (points[((size_t)b * NPTS + pid) * 3 + c] - refc[q * 3 + c]) * 5.0f;
        } else {
            val = features[((size_t)b * NPTS + pid) * 128 + (c - 3)];
        }
        x0[rr * X0_STRIDE + c] = val;
    }
    __syncthreads();

    int ty = t >> 4;     // 0..15 -> 8 rows each
    int tx = t & 15;
    int r0 = ty * 8;

    // ---- layer1: 128x64, microtile 8 rows x 4 cols (2 f32x2 pairs) ----
    {
        int c0 = tx * 4;
        unsigned long long acc2[8][2];
        #pragma unroll
        for (int i = 0; i < 8; i++) { acc2[i][0] = 0ull; acc2[i][1] = 0ull; }

        const float* x0r = x0 + r0 * X0_STRIDE;
        for (int k = 0; k < 131; k++) {
            ulonglong2 w = *(const ulonglong2*)(W1s + k * 64 + c0);
            #pragma unroll
            for (int i = 0; i < 8; i++) {
                unsigned long long aa = dup_f32(x0r[i * X0_STRIDE + k]);
                fma2(acc2[i][0], aa, w.x);
                fma2(acc2[i][1], aa, w.y);
            }
        }
        #pragma unroll
        for (int jp = 0; jp < 2; jp++) {
            float s0 = sc1[c0 + 2 * jp],     h0 = sh1[c0 + 2 * jp];
            float s1 = sc1[c0 + 2 * jp + 1], h1 = sh1[c0 + 2 * jp + 1];
            #pragma unroll
            for (int i = 0; i < 8; i++) {
                float2 v = unpack_f32x2(acc2[i][jp]);
                x1[(r0 + i) * X1_STRIDE + c0 + 2 * jp]     = fmaxf(fmaf(v.x, s0, h0), 0.0f);
                x1[(r0 + i) * X1_STRIDE + c0 + 2 * jp + 1] = fmaxf(fmaf(v.y, s1, h1), 0.0f);
            }
        }
    }
    __syncthreads();

    // ---- layer2: 128x128, microtile 8x8 (4 f32x2 pairs) ----
    {
        int c0 = tx * 8;
        unsigned long long acc2[8][4];
        #pragma unroll
        for (int i = 0; i < 8; i++)
            #pragma unroll
            for (int j = 0; j < 4; j++) acc2[i][j] = 0ull;

        const float* x1r = x1 + r0 * X1_STRIDE;
        #pragma unroll 4
        for (int k = 0; k < 64; k++) {
            ulonglong2 wA = *(const ulonglong2*)(W2s + k * 128 + c0);
            ulonglong2 wB = *(const ulonglong2*)(W2s + k * 128 + c0 + 4);
            #pragma unroll
            for (int i = 0; i < 8; i++) {
                unsigned long long aa = dup_f32(x1r[i * X1_STRIDE + k]);
                fma2(acc2[i][0], aa, wA.x);
                fma2(acc2[i][1], aa, wA.y);
                fma2(acc2[i][2], aa, wB.x);
                fma2(acc2[i][3], aa, wB.y);
            }
        }
        #pragma unroll
        for (int i = 0; i < 8; i++) {
            size_t row = (size_t)g * 128 + r0 + i;
            float o[8];
            #pragma unroll
            for (int jp = 0; jp < 4; jp++) {
                float2 v = unpack_f32x2(acc2[i][jp]);
                int j0 = 2 * jp;
                o[j0]     = fmaxf(fmaf(v.x, sc2[c0 + j0],     sh2[c0 + j0]),     0.0f);
                o[j0 + 1] = fmaxf(fmaf(v.y, sc2[c0 + j0 + 1], sh2[c0 + j0 + 1]), 0.0f);
            }
            float4 v0 = make_float4(o[0], o[1], o[2], o[3]);
            float4 v1v = make_float4(o[4], o[5], o[6], o[7]);
            *(float4*)&g_x2[row * 128 + c0] = v0;
            *(float4*)&g_x2[row * 128 + c0 + 4] = v1v;
        }
    }
}

// =====================================================================
// Kernel 3: layer3 (128->256) + BN + ReLU + max over K=32 rows.
// Block tile: 128 rows (= 4 refs) x 128 cols. grid = (1024, 2). f32x2.
// =====================================================================
#define AS_STRIDE 133
#define WS_STRIDE 132

#define SM3_A   0                           // 128*133 = 17024
#define SM3_W   (SM3_A + 128*AS_STRIDE)     // 128*132 = 16896
#define SM3_RED (SM3_W + 128*WS_STRIDE)     // 16*128 = 2048
#define SM3_SC  (SM3_RED + 16*128)          // 128
#define SM3_SH  (SM3_SC + 128)              // 128
#define SM3_TOTAL ((SM3_SH + 128) * 4)

__global__ __launch_bounds__(256) void mlp3_kernel(
    const float* __restrict__ W3, const float* __restrict__ g3,
    const float* __restrict__ b3, const float* __restrict__ m3,
    const float* __restrict__ v3, float* __restrict__ out)
{
    extern __shared__ float sm[];
    float* As  = sm + SM3_A;
    float* Ws  = sm + SM3_W;
    float* red = sm + SM3_RED;
    float* sc3 = sm + SM3_SC;
    float* sh3 = sm + SM3_SH;

    int t = threadIdx.x;
    int g = blockIdx.x;          // row group: rows [g*128, g*128+128)
    int colbase = blockIdx.y * 128;

    // load A tile [128 rows][128 k]
    for (int e4 = t; e4 < 128 * 32; e4 += 256) {
        int row = e4 >> 5;
        int k4 = (e4 & 31) << 2;
        float4 v = *(const float4*)&g_x2[((size_t)g * 128 + row) * 128 + k4];
        float* dst = As + row * AS_STRIDE + k4;
        dst[0] = v.x; dst[1] = v.y; dst[2] = v.z; dst[3] = v.w;
    }
    // load W tile [128 k][128 cols]
    for (int e4 = t; e4 < 128 * 32; e4 += 256) {
        int k = e4 >> 5;
        int c4 = (e4 & 31) << 2;
        float4 v = *(const float4*)&W3[k * 256 + colbase + c4];
        *(float4*)&Ws[k * WS_STRIDE + c4] = v;
    }
    if (t < 128) {
        int j = colbase + t;
        float s = g3[j] * rsqrtf(v3[j] + 1e-5f);
        sc3[t] = s; sh3[t] = b3[j] - m3[j] * s;
    }
    __syncthreads();

    int ty = t >> 4;     // rows 8*ty..8*ty+7 (within one ref's 32 rows)
    int tx = t & 15;     // cols 8*tx..8*tx+7
    int r0 = ty * 8;
    int c0 = tx * 8;

    unsigned long long acc2[8][4];
    #pragma unroll
    for (int i = 0; i < 8; i++)
        #pragma unroll
        for (int j = 0; j < 4; j++) acc2[i][j] = 0ull;

    const float* Ar = As + r0 * AS_STRIDE;
    #pragma unroll 4
    for (int k = 0; k < 128; k++) {
        ulonglong2 wA = *(const ulonglong2*)(Ws + k * WS_STRIDE + c0);
        ulonglong2 wB = *(const ulonglong2*)(Ws + k * WS_STRIDE + c0 + 4);
        #pragma unroll
        for (int i = 0; i < 8; i++) {
            unsigned long long aa = dup_f32(Ar[i * AS_STRIDE + k]);
            fma2(acc2[i][0], aa, wA.x);
            fma2(acc2[i][1], aa, wA.y);
            fma2(acc2[i][2], aa, wB.x);
            fma2(acc2[i][3], aa, wB.y);
        }
    }

    // BN + ReLU + max over this thread's 8 rows (all within one ref)
    #pragma unroll
    for (int jp = 0; jp < 4; jp++) {
        int j0 = 2 * jp;
        float s0 = sc3[c0 + j0],     h0 = sh3[c0 + j0];
        float s1 = sc3[c0 + j0 + 1], h1 = sh3[c0 + j0 + 1];
        float mx0 = 0.0f, mx1 = 0.0f;   // ReLU => >= 0
        #pragma unroll
        for (int i = 0; i < 8; i++) {
            float2 v = unpack_f32x2(acc2[i][jp]);
            mx0 = fmaxf(mx0, fmaxf(fmaf(v.x, s0, h0), 0.0f));
            mx1 = fmaxf(mx1, fmaxf(fmaf(v.y, s1, h1), 0.0f));
        }
        red[ty * 128 + c0 + j0] = mx0;
        red[ty * 128 + c0 + j0 + 1] = mx1;
    }
    __syncthreads();

    // combine 4 ty-groups per ref (32 rows per ref), write output
    for (int o = t; o < 512; o += 256) {
        int q = o >> 7;          // ref within group (0..3)
        int col = o & 127;
        float v = red[(4 * q + 0) * 128 + col];
        v = fmaxf(v, red[(4 * q + 1) * 128 + col]);
        v = fmaxf(v, red[(4 * q + 2) * 128 + col]);
        v = fmaxf(v, red[(4 * q + 3) * 128 + col]);
        out[((size_t)g * 4 + q) * 256 + colbase + col] = v;
    }
}

// =====================================================================
extern "C" void kernel_launch(void* const* d_in, const int* in_sizes, int n_in,
                              void* d_out, int out_size)
{
    const float* points   = (const float*)d_in[0];
    const float* features = (const float*)d_in[1];
    const float* refs     = (const float*)d_in[2];
    const float* W1 = (const float*)d_in[3];
    const float* g1 = (const float*)d_in[4];
    const float* b1 = (const float*)d_in[5];
    const float* m1 = (const float*)d_in[6];
    const float* v1 = (const float*)d_in[7];
    const float* W2 = (const float*)d_in[8];
    const float* g2 = (const float*)d_in[9];
    const float* b2 = (const float*)d_in[10];
    const float* m2 = (const float*)d_in[11];
    const float* v2 = (const float*)d_in[12];
    const float* W3 = (const float*)d_in[13];
    const float* g3 = (const float*)d_in[14];
    const float* b3 = (const float*)d_in[15];
    const float* m3 = (const float*)d_in[16];
    const float* v3 = (const float*)d_in[17];
    float* out = (float*)d_out;

    cudaFuncSetAttribute(mlp12_kernel, cudaFuncAttributeMaxDynamicSharedMemorySize, SM2_TOTAL);
    cudaFuncSetAttribute(mlp3_kernel,  cudaFuncAttributeMaxDynamicSharedMemorySize, SM3_TOTAL);

    ball_query_kernel<<<NREF / 8, 256>>>(points, refs);
    mlp12_kernel<<<NREF / 4, 256, SM2_TOTAL>>>(points, features, refs,
                                               W1, g1, b1, m1, v1,
                                               W2, g2, b2, m2, v2);
    mlp3_kernel<<<dim3(NREF / 4, 2), 256, SM3_TOTAL>>>(W3, g3, b3, m3, v3, out);
}

// round 8
// speedup vs baseline: 1.4829x; 1.2356x over previous
#include <cuda_runtime.h>
#include <cuda_bf16.h>
#include <math.h>
#include <stdint.h>

#define BATCH 4
#define NPTS 20000
#define NS 1024
#define NC 128
#define NK 32
#define NREF (BATCH * NS)   // 4096

// ---------------- scratch (static device globals; no allocations) ----------------
__device__ int   g_idx[NREF * NK];                         // 512 KB
__device__ float g_x2[(size_t)NREF * NK * 128];            // 64 MiB

// ---------------- packed f32x2 helpers ----------------
__device__ __forceinline__ unsigned long long dup_f32(float a) {
    unsigned long long r;
    asm("mov.b64 %0, {%1, %1};" : "=l"(r) : "r"(__float_as_uint(a)));
    return r;
}
__device__ __forceinline__ void fma2(unsigned long long& acc,
                                     unsigned long long a, unsigned long long w) {
    asm("fma.rn.f32x2 %0, %1, %2, %0;" : "+l"(acc) : "l"(a), "l"(w));
}
__device__ __forceinline__ float2 unpack_f32x2(unsigned long long v) {
    unsigned lo, hi;
    asm("mov.b64 {%0, %1}, %2;" : "=r"(lo), "=r"(hi) : "l"(v));
    return make_float2(__uint_as_float(lo), __uint_as_float(hi));
}

// ---------------- mma.sync bf16 (m16n8k16, fp32 accum) ----------------
__device__ __forceinline__ void mma_bf16(float* d, const uint32_t* a, const uint32_t* b) {
    asm volatile(
        "mma.sync.aligned.m16n8k16.row.col.f32.bf16.bf16.f32 "
        "{%0,%1,%2,%3}, {%4,%5,%6,%7}, {%8,%9}, {%0,%1,%2,%3};"
        : "+f"(d[0]), "+f"(d[1]), "+f"(d[2]), "+f"(d[3])
        : "r"(a[0]), "r"(a[1]), "r"(a[2]), "r"(a[3]), "r"(b[0]), "r"(b[1]));
}

// =====================================================================
// Kernel 1: ball query (unchanged; 29us measured).
// =====================================================================
__global__ __launch_bounds__(256) void ball_query_kernel(
    const float* __restrict__ points, const float* __restrict__ refs)
{
    int warp = (blockIdx.x * 256 + threadIdx.x) >> 5;
    int lane = threadIdx.x & 31;
    if (warp >= NREF) return;
    int b = warp >> 10;
    const float* rp = refs + (size_t)warp * 3;
    float rx = rp[0], ry = rp[1], rz = rp[2];
    float rr2 = rx * rx + ry * ry + rz * rz;
    const float R2 = 0.2f * 0.2f;
    int* out = g_idx + warp * NK;
    const float* pbase = points + (size_t)b * NPTS * 3;

    int count = 0;
    int first = -1;
    for (int base = 0; base < NPTS && count < NK; base += 128) {
        float px[4], py[4], pz[4];
        #pragma unroll
        for (int j = 0; j < 4; j++) {
            int i = base + j * 32 + lane;
            bool valid = (i < NPTS);
            int ii = valid ? i : 0;
            px[j] = pbase[ii * 3 + 0];
            py[j] = pbase[ii * 3 + 1];
            pz[j] = pbase[ii * 3 + 2];
            if (!valid) { px[j] = 1e9f; }
        }
        #pragma unroll
        for (int j = 0; j < 4; j++) {
            int i = base + j * 32 + lane;
            float pp2 = px[j] * px[j] + py[j] * py[j] + pz[j] * pz[j];
            float dot = rx * px[j] + ry * py[j] + rz * pz[j];
            float d2 = rr2 + pp2 - 2.0f * dot;
            bool pred = d2 < R2;
            unsigned m = __ballot_sync(0xffffffffu, pred);
            if (m) {
                if (first < 0) first = __shfl_sync(0xffffffffu, i, __ffs(m) - 1);
                if (pred) {
                    int rank = __popc(m & ((1u << lane) - 1u));
                    int slot = count + rank;
                    if (slot < NK) out[slot] = i;
                }
                count += __popc(m);
            }
        }
    }
    if (count < NK) {
        int fill = (count == 0) ? (NPTS - 1) : first;
        if (lane >= count) out[lane] = fill;
    }
}

// =====================================================================
// Kernel 2: gather + layer1 + layer2 (f32x2; unchanged from R5).
// =====================================================================
#define X0_STRIDE 133
#define X1_STRIDE 69

#define SM2_W1   0
#define SM2_W2   (SM2_W1 + 131*64)
#define SM2_X0   (SM2_W2 + 64*128)
#define SM2_X1   (SM2_X0 + 128*X0_STRIDE)
#define SM2_SC1  (SM2_X1 + 128*X1_STRIDE)
#define SM2_SH1  (SM2_SC1 + 64)
#define SM2_SC2  (SM2_SH1 + 64)
#define SM2_SH2  (SM2_SC2 + 128)
#define SM2_REFC (SM2_SH2 + 128)
#define SM2_TOTAL ((SM2_REFC + 16) * 4)

__global__ __launch_bounds__(256) void mlp12_kernel(
    const float* __restrict__ points, const float* __restrict__ features,
    const float* __restrict__ refs,
    const float* __restrict__ W1, const float* __restrict__ g1,
    const float* __restrict__ b1, const float* __restrict__ m1,
    const float* __restrict__ v1,
    const float* __restrict__ W2, const float* __restrict__ g2,
    const float* __restrict__ b2, const float* __restrict__ m2,
    const float* __restrict__ v2)
{
    extern __shared__ float sm[];
    float* W1s = sm + SM2_W1;
    float* W2s = sm + SM2_W2;
    float* x0  = sm + SM2_X0;
    float* x1  = sm + SM2_X1;
    float* sc1 = sm + SM2_SC1;
    float* sh1 = sm + SM2_SH1;
    float* sc2 = sm + SM2_SC2;
    float* sh2 = sm + SM2_SH2;
    float* refc = sm + SM2_REFC;

    int t = threadIdx.x;
    int g = blockIdx.x;
    int ref0 = g * 4;
    int b = ref0 >> 10;

    for (int e = t; e < 131 * 64; e += 256) W1s[e] = W1[e];
    for (int e = t; e < 64 * 128; e += 256) W2s[e] = W2[e];
    if (t < 64) {
        float s = g1[t] * rsqrtf(v1[t] + 1e-5f);
        sc1[t] = s; sh1[t] = b1[t] - m1[t] * s;
    } else if (t < 192) {
        int j = t - 64;
        float s = g2[j] * rsqrtf(v2[j] + 1e-5f);
        sc2[j] = s; sh2[j] = b2[j] - m2[j] * s;
    }
    if (t < 12) refc[t] = refs[(size_t)ref0 * 3 + t];
    __syncthreads();

    const int E = 128 * 131;
    for (int e = t; e < E; e += 256) {
        int rr = e / 131;
        int c = e - rr * 131;
        int q = rr >> 5, kk = rr & 31;
        int pid = g_idx[(ref0 + q) * NK + kk];
        float val;
        if (c < 3) {
            val = (points[((size_t)b * NPTS + pid) * 3 + c] - refc[q * 3 + c]) * 5.0f;
        } else {
            val = features[((size_t)b * NPTS + pid) * 128 + (c - 3)];
        }
        x0[rr * X0_STRIDE + c] = val;
    }
    __syncthreads();

    int ty = t >> 4;
    int tx = t & 15;
    int r0 = ty * 8;

    {
        int c0 = tx * 4;
        unsigned long long acc2[8][2];
        #pragma unroll
        for (int i = 0; i < 8; i++) { acc2[i][0] = 0ull; acc2[i][1] = 0ull; }

        const float* x0r = x0 + r0 * X0_STRIDE;
        for (int k = 0; k < 131; k++) {
            ulonglong2 w = *(const ulonglong2*)(W1s + k * 64 + c0);
            #pragma unroll
            for (int i = 0; i < 8; i++) {
                unsigned long long aa = dup_f32(x0r[i * X0_STRIDE + k]);
                fma2(acc2[i][0], aa, w.x);
                fma2(acc2[i][1], aa, w.y);
            }
        }
        #pragma unroll
        for (int jp = 0; jp < 2; jp++) {
            float s0 = sc1[c0 + 2 * jp],     h0 = sh1[c0 + 2 * jp];
            float s1 = sc1[c0 + 2 * jp + 1], h1 = sh1[c0 + 2 * jp + 1];
            #pragma unroll
            for (int i = 0; i < 8; i++) {
                float2 v = unpack_f32x2(acc2[i][jp]);
                x1[(r0 + i) * X1_STRIDE + c0 + 2 * jp]     = fmaxf(fmaf(v.x, s0, h0), 0.0f);
                x1[(r0 + i) * X1_STRIDE + c0 + 2 * jp + 1] = fmaxf(fmaf(v.y, s1, h1), 0.0f);
            }
        }
    }
    __syncthreads();

    {
        int c0 = tx * 8;
        unsigned long long acc2[8][4];
        #pragma unroll
        for (int i = 0; i < 8; i++)
            #pragma unroll
            for (int j = 0; j < 4; j++) acc2[i][j] = 0ull;

        const float* x1r = x1 + r0 * X1_STRIDE;
        #pragma unroll 4
        for (int k = 0; k < 64; k++) {
            ulonglong2 wA = *(const ulonglong2*)(W2s + k * 128 + c0);
            ulonglong2 wB = *(const ulonglong2*)(W2s + k * 128 + c0 + 4);
            #pragma unroll
            for (int i = 0; i < 8; i++) {
                unsigned long long aa = dup_f32(x1r[i * X1_STRIDE + k]);
                fma2(acc2[i][0], aa, wA.x);
                fma2(acc2[i][1], aa, wA.y);
                fma2(acc2[i][2], aa, wB.x);
                fma2(acc2[i][3], aa, wB.y);
            }
        }
        #pragma unroll
        for (int i = 0; i < 8; i++) {
            size_t row = (size_t)g * 128 + r0 + i;
            float o[8];
            #pragma unroll
            for (int jp = 0; jp < 4; jp++) {
                float2 v = unpack_f32x2(acc2[i][jp]);
                int j0 = 2 * jp;
                o[j0]     = fmaxf(fmaf(v.x, sc2[c0 + j0],     sh2[c0 + j0]),     0.0f);
                o[j0 + 1] = fmaxf(fmaf(v.y, sc2[c0 + j0 + 1], sh2[c0 + j0 + 1]), 0.0f);
            }
            float4 v0 = make_float4(o[0], o[1], o[2], o[3]);
            float4 v1v = make_float4(o[4], o[5], o[6], o[7]);
            *(float4*)&g_x2[row * 128 + c0] = v0;
            *(float4*)&g_x2[row * 128 + c0 + 4] = v1v;
        }
    }
}

// =====================================================================
// Kernel 3: layer3 via mma.sync bf16 3-pass split + fused BN/ReLU/max.
// Grid (1024, 2), 256 threads. CTA tile: 128 rows (4 refs) x 128 cols.
// Warp tile: 32 rows (one ref) x 64 cols -> 2 m-tiles x 8 n-tiles.
// =====================================================================
#define BF_STRIDE 136   // bf16 elems per row; 136*2B = 272B -> conflict-free frags
#define S3B_AHI 0
#define S3B_ALO (S3B_AHI + 128*BF_STRIDE*2)   // 34816
#define S3B_BHI (S3B_ALO + 128*BF_STRIDE*2)   // 69632
#define S3B_BLO (S3B_BHI + 128*BF_STRIDE*2)   // 104448
#define S3B_SC  (S3B_BLO + 128*BF_STRIDE*2)   // 139264
#define S3B_SH  (S3B_SC + 128*4)              // 139776
#define S3B_TOTAL (S3B_SH + 128*4)            // 140288

__global__ __launch_bounds__(256) void mlp3_mma_kernel(
    const float* __restrict__ W3, const float* __restrict__ g3,
    const float* __restrict__ b3, const float* __restrict__ m3,
    const float* __restrict__ v3, float* __restrict__ out)
{
    extern __shared__ char smc[];
    __nv_bfloat16* Ahi = (__nv_bfloat16*)(smc + S3B_AHI);
    __nv_bfloat16* Alo = (__nv_bfloat16*)(smc + S3B_ALO);
    __nv_bfloat16* Bhi = (__nv_bfloat16*)(smc + S3B_BHI);
    __nv_bfloat16* Blo = (__nv_bfloat16*)(smc + S3B_BLO);
    float* scs = (float*)(smc + S3B_SC);
    float* shs = (float*)(smc + S3B_SH);

    int t = threadIdx.x;
    int lane = t & 31, wid = t >> 5;
    int g = blockIdx.x;
    int colbase = blockIdx.y * 128;

    if (t < 128) {
        int j = colbase + t;
        float s = g3[j] * rsqrtf(v3[j] + 1e-5f);
        scs[t] = s;
        shs[t] = b3[j] - m3[j] * s;
    }

    // ---- stage A = x2 rows (hi/lo bf16) ----
    for (int e = t; e < 128 * 32; e += 256) {
        int row = e >> 5;
        int k4 = (e & 31) << 2;
        float4 v = *(const float4*)&g_x2[((size_t)g * 128 + row) * 128 + k4];
        float vv[4] = {v.x, v.y, v.z, v.w};
        #pragma unroll
        for (int j = 0; j < 4; j++) {
            __nv_bfloat16 h = __float2bfloat16_rn(vv[j]);
            __nv_bfloat16 l = __float2bfloat16_rn(vv[j] - __bfloat162float(h));
            Ahi[row * BF_STRIDE + k4 + j] = h;
            Alo[row * BF_STRIDE + k4 + j] = l;
        }
    }
    // ---- stage B = W3^T (hi/lo bf16), B[n][k] ----
    for (int e = t; e < 128 * 128; e += 256) {
        int k = e >> 7, n = e & 127;
        float w = W3[k * 256 + colbase + n];
        __nv_bfloat16 h = __float2bfloat16_rn(w);
        __nv_bfloat16 l = __float2bfloat16_rn(w - __bfloat162float(h));
        Bhi[n * BF_STRIDE + k] = h;
        Blo[n * BF_STRIDE + k] = l;
    }
    __syncthreads();

    int r0 = (wid >> 1) * 32;       // warp's ref rows
    int c0 = (wid & 1) * 64;        // warp's col half
    int q  = wid >> 1;              // ref within group

    float d[2][8][4];
    #pragma unroll
    for (int mi = 0; mi < 2; mi++)
        #pragma unroll
        for (int ni = 0; ni < 8; ni++)
            #pragma unroll
            for (int e = 0; e < 4; e++) d[mi][ni][e] = 0.0f;

    int rl = lane >> 2;             // 0..7
    int cl = (lane & 3) * 2;        // 0,2,4,6

    for (int ks = 0; ks < 8; ks++) {
        int k0 = ks * 16;
        uint32_t ahi[2][4], alo[2][4];
        #pragma unroll
        for (int mi = 0; mi < 2; mi++) {
            int r = r0 + mi * 16 + rl;
            int c = k0 + cl;
            ahi[mi][0] = *(const uint32_t*)&Ahi[r * BF_STRIDE + c];
            ahi[mi][1] = *(const uint32_t*)&Ahi[(r + 8) * BF_STRIDE + c];
            ahi[mi][2] = *(const uint32_t*)&Ahi[r * BF_STRIDE + c + 8];
            ahi[mi][3] = *(const uint32_t*)&Ahi[(r + 8) * BF_STRIDE + c + 8];
            alo[mi][0] = *(const uint32_t*)&Alo[r * BF_STRIDE + c];
            alo[mi][1] = *(const uint32_t*)&Alo[(r + 8) * BF_STRIDE + c];
            alo[mi][2] = *(const uint32_t*)&Alo[r * BF_STRIDE + c + 8];
            alo[mi][3] = *(const uint32_t*)&Alo[(r + 8) * BF_STRIDE + c + 8];
        }
        uint32_t bhi[8][2], blo[8][2];
        #pragma unroll
        for (int ni = 0; ni < 8; ni++) {
            int n = c0 + ni * 8 + rl;
            int k = k0 + cl;
            bhi[ni][0] = *(const uint32_t*)&Bhi[n * BF_STRIDE + k];
            bhi[ni][1] = *(const uint32_t*)&Bhi[n * BF_STRIDE + k + 8];
            blo[ni][0] = *(const uint32_t*)&Blo[n * BF_STRIDE + k];
            blo[ni][1] = *(const uint32_t*)&Blo[n * BF_STRIDE + k + 8];
        }
        #pragma unroll
        for (int mi = 0; mi < 2; mi++)
            #pragma unroll
            for (int ni = 0; ni < 8; ni++) {
                mma_bf16(d[mi][ni], ahi[mi], bhi[ni]);
                mma_bf16(d[mi][ni], ahi[mi], blo[ni]);
                mma_bf16(d[mi][ni], alo[mi], bhi[ni]);
            }
    }

    // ---- epilogue: BN + ReLU + max over this warp's 32 rows (one ref) ----
    #pragma unroll
    for (int ni = 0; ni < 8; ni++) {
        #pragma unroll
        for (int e = 0; e < 2; e++) {
            int col = c0 + ni * 8 + cl + e;
            float s = scs[col], h = shs[col];
            float mx = 0.0f;   // ReLU => >= 0
            #pragma unroll
            for (int mi = 0; mi < 2; mi++) {
                mx = fmaxf(mx, fmaxf(fmaf(d[mi][ni][e],     s, h), 0.0f));
                mx = fmaxf(mx, fmaxf(fmaf(d[mi][ni][2 + e], s, h), 0.0f));
            }
            // reduce across the 8 row-lanes (lane>>2 varies; lane&3 fixed)
            mx = fmaxf(mx, __shfl_xor_sync(0xffffffffu, mx, 4));
            mx = fmaxf(mx, __shfl_xor_sync(0xffffffffu, mx, 8));
            mx = fmaxf(mx, __shfl_xor_sync(0xffffffffu, mx, 16));
            if (lane < 4)
                out[((size_t)g * 4 + q) * 256 + colbase + col] = mx;
        }
    }
}

// =====================================================================
extern "C" void kernel_launch(void* const* d_in, const int* in_sizes, int n_in,
                              void* d_out, int out_size)
{
    const float* points   = (const float*)d_in[0];
    const float* features = (const float*)d_in[1];
    const float* refs     = (const float*)d_in[2];
    const float* W1 = (const float*)d_in[3];
    const float* g1 = (const float*)d_in[4];
    const float* b1 = (const float*)d_in[5];
    const float* m1 = (const float*)d_in[6];
    const float* v1 = (const float*)d_in[7];
    const float* W2 = (const float*)d_in[8];
    const float* g2 = (const float*)d_in[9];
    const float* b2 = (const float*)d_in[10];
    const float* m2 = (const float*)d_in[11];
    const float* v2 = (const float*)d_in[12];
    const float* W3 = (const float*)d_in[13];
    const float* g3 = (const float*)d_in[14];
    const float* b3 = (const float*)d_in[15];
    const float* m3 = (const float*)d_in[16];
    const float* v3 = (const float*)d_in[17];
    float* out = (float*)d_out;

    cudaFuncSetAttribute(mlp12_kernel,    cudaFuncAttributeMaxDynamicSharedMemorySize, SM2_TOTAL);
    cudaFuncSetAttribute(mlp3_mma_kernel, cudaFuncAttributeMaxDynamicSharedMemorySize, S3B_TOTAL);

    ball_query_kernel<<<NREF / 8, 256>>>(points, refs);
    mlp12_kernel<<<NREF / 4, 256, SM2_TOTAL>>>(points, features, refs,
                                               W1, g1, b1, m1, v1,
                                               W2, g2, b2, m2, v2);
    mlp3_mma_kernel<<<dim3(NREF / 4, 2), 256, S3B_TOTAL>>>(W3, g3, b3, m3, v3, out);
}

// round 10
// speedup vs baseline: 1.5150x; 1.0217x over previous
#include <cuda_runtime.h>
#include <cuda_bf16.h>
#include <math.h>
#include <stdint.h>

#define BATCH 4
#define NPTS 20000
#define NS 1024
#define NC 128
#define NK 32
#define NREF (BATCH * NS)   // 4096

// ---------------- scratch (static device globals; no allocations) ----------------
__device__ int   g_idx[NREF * NK];                         // 512 KB
__device__ float g_x2[(size_t)NREF * NK * 128];            // 64 MiB

// ---------------- mma.sync bf16 (m16n8k16, fp32 accum) ----------------
__device__ __forceinline__ void mma_bf16(float* d, const uint32_t* a, const uint32_t* b) {
    asm volatile(
        "mma.sync.aligned.m16n8k16.row.col.f32.bf16.bf16.f32 "
        "{%0,%1,%2,%3}, {%4,%5,%6,%7}, {%8,%9}, {%0,%1,%2,%3};"
        : "+f"(d[0]), "+f"(d[1]), "+f"(d[2]), "+f"(d[3])
        : "r"(a[0]), "r"(a[1]), "r"(a[2]), "r"(a[3]), "r"(b[0]), "r"(b[1]));
}
__device__ __forceinline__ uint32_t pack_bf2(__nv_bfloat16 a, __nv_bfloat16 b) {
    uint32_t r;
    uint16_t ua = *(uint16_t*)&a, ub = *(uint16_t*)&b;
    r = (uint32_t)ua | ((uint32_t)ub << 16);
    return r;
}

// =====================================================================
// Kernel 1: ball query (unchanged; 29us measured).
// =====================================================================
__global__ __launch_bounds__(256) void ball_query_kernel(
    const float* __restrict__ points, const float* __restrict__ refs)
{
    int warp = (blockIdx.x * 256 + threadIdx.x) >> 5;
    int lane = threadIdx.x & 31;
    if (warp >= NREF) return;
    int b = warp >> 10;
    const float* rp = refs + (size_t)warp * 3;
    float rx = rp[0], ry = rp[1], rz = rp[2];
    float rr2 = rx * rx + ry * ry + rz * rz;
    const float R2 = 0.2f * 0.2f;
    int* out = g_idx + warp * NK;
    const float* pbase = points + (size_t)b * NPTS * 3;

    int count = 0;
    int first = -1;
    for (int base = 0; base < NPTS && count < NK; base += 128) {
        float px[4], py[4], pz[4];
        #pragma unroll
        for (int j = 0; j < 4; j++) {
            int i = base + j * 32 + lane;
            bool valid = (i < NPTS);
            int ii = valid ? i : 0;
            px[j] = pbase[ii * 3 + 0];
            py[j] = pbase[ii * 3 + 1];
            pz[j] = pbase[ii * 3 + 2];
            if (!valid) { px[j] = 1e9f; }
        }
        #pragma unroll
        for (int j = 0; j < 4; j++) {
            int i = base + j * 32 + lane;
            float pp2 = px[j] * px[j] + py[j] * py[j] + pz[j] * pz[j];
            float dot = rx * px[j] + ry * py[j] + rz * pz[j];
            float d2 = rr2 + pp2 - 2.0f * dot;
            bool pred = d2 < R2;
            unsigned m = __ballot_sync(0xffffffffu, pred);
            if (m) {
                if (first < 0) first = __shfl_sync(0xffffffffu, i, __ffs(m) - 1);
                if (pred) {
                    int rank = __popc(m & ((1u << lane) - 1u));
                    int slot = count + rank;
                    if (slot < NK) out[slot] = i;
                }
                count += __popc(m);
            }
        }
    }
    if (count < NK) {
        int fill = (count == 0) ? (NPTS - 1) : first;
        if (lane >= count) out[lane] = fill;
    }
}

// =====================================================================
// Kernel 2: gather + layer1 (K padded 131->144) + layer2, both via
// mma.sync bf16 3-pass split. One block = 4 refs = 128 rows, 256 thr.
// =====================================================================
#define A0_STR 152   // bf16/row for x0 (144 + pad) -> conflict-free frags
#define B1_STR 152
#define X1_STR 72    // bf16/row for x1 (64 + pad)
#define B2_STR 72

// smem byte offsets
#define SB_A0HI 0                              // 128*152*2 = 38912
#define SB_A0LO (SB_A0HI + 128*A0_STR*2)       // 38912
#define SB_B1HI (SB_A0LO + 128*A0_STR*2)       // 77824; 64*152*2 = 19456
#define SB_B1LO (SB_B1HI + 64*B1_STR*2)        // 97280
#define SB_X1HI (SB_B1LO + 64*B1_STR*2)        // 116736; 128*72*2 = 18432
#define SB_X1LO (SB_X1HI + 128*X1_STR*2)       // 135168
#define SB_B2HI (SB_X1LO + 128*X1_STR*2)       // 153600
#define SB_B2LO (SB_B2HI + 128*B2_STR*2)       // 172032
#define SB_SC1  (SB_B2LO + 128*B2_STR*2)       // 190464
#define SB_SH1  (SB_SC1 + 64*4)                // 190720
#define SB_SC2  (SB_SH1 + 64*4)                // 190976
#define SB_SH2  (SB_SC2 + 128*4)               // 191488
#define SB_TOT  (SB_SH2 + 128*4)               // 192000

__global__ __launch_bounds__(256) void mlp12_mma_kernel(
    const float* __restrict__ points, const float* __restrict__ features,
    const float* __restrict__ refs,
    const float* __restrict__ W1, const float* __restrict__ g1,
    const float* __restrict__ b1, const float* __restrict__ m1,
    const float* __restrict__ v1,
    const float* __restrict__ W2, const float* __restrict__ g2,
    const float* __restrict__ b2, const float* __restrict__ m2,
    const float* __restrict__ v2)
{
    extern __shared__ char smc[];
    __nv_bfloat16* A0hi = (__nv_bfloat16*)(smc + SB_A0HI);
    __nv_bfloat16* A0lo = (__nv_bfloat16*)(smc + SB_A0LO);
    __nv_bfloat16* B1hi = (__nv_bfloat16*)(smc + SB_B1HI);
    __nv_bfloat16* B1lo = (__nv_bfloat16*)(smc + SB_B1LO);
    __nv_bfloat16* X1hi = (__nv_bfloat16*)(smc + SB_X1HI);
    __nv_bfloat16* X1lo = (__nv_bfloat16*)(smc + SB_X1LO);
    __nv_bfloat16* B2hi = (__nv_bfloat16*)(smc + SB_B2HI);
    __nv_bfloat16* B2lo = (__nv_bfloat16*)(smc + SB_B2LO);
    float* sc1s = (float*)(smc + SB_SC1);
    float* sh1s = (float*)(smc + SB_SH1);
    float* sc2s = (float*)(smc + SB_SC2);
    float* sh2s = (float*)(smc + SB_SH2);

    int t = threadIdx.x;
    int lane = t & 31, w = t >> 5;
    int g = blockIdx.x;
    int ref0 = g * 4;
    int b = ref0 >> 10;

    // ---- BN coefficients ----
    if (t < 64) {
        float s = g1[t] * rsqrtf(v1[t] + 1e-5f);
        sc1s[t] = s; sh1s[t] = b1[t] - m1[t] * s;
    } else if (t < 192) {
        int j = t - 64;
        float s = g2[j] * rsqrtf(v2[j] + 1e-5f);
        sc2s[j] = s; sh2s[j] = b2[j] - m2[j] * s;
    }

    // ---- stage B1 = W1^T (64 n x 144 k, hi/lo; k>=131 zero) ----
    for (int e = t; e < 64 * 144; e += 256) {
        int k = e >> 6, n = e & 63;
        float wv = (k < 131) ? W1[k * 64 + n] : 0.0f;
        __nv_bfloat16 h = __float2bfloat16_rn(wv);
        __nv_bfloat16 l = __float2bfloat16_rn(wv - __bfloat162float(h));
        B1hi[n * B1_STR + k] = h;
        B1lo[n * B1_STR + k] = l;
    }
    // ---- stage B2 = W2^T (128 n x 64 k, hi/lo) ----
    for (int e = t; e < 128 * 64; e += 256) {
        int k = e >> 7, n = e & 127;
        float wv = W2[k * 128 + n];
        __nv_bfloat16 h = __float2bfloat16_rn(wv);
        __nv_bfloat16 l = __float2bfloat16_rn(wv - __bfloat162float(h));
        B2hi[n * B2_STR + k] = h;
        B2lo[n * B2_STR + k] = l;
    }
    // ---- zero pad cols 131..143 of x0 ----
    for (int e = t; e < 128 * 13; e += 256) {
        int rr = e / 13, c = 131 + e % 13;
        A0hi[rr * A0_STR + c] = __float2bfloat16_rn(0.0f);
        A0lo[rr * A0_STR + c] = __float2bfloat16_rn(0.0f);
    }
    // ---- gather x0 (hi/lo bf16) ----
    for (int e = t; e < 128 * 131; e += 256) {
        int rr = e / 131;
        int c = e - rr * 131;
        int q = rr >> 5, kk = rr & 31;
        int pid = g_idx[(ref0 + q) * NK + kk];
        float val;
        if (c < 3) {
            val = (points[((size_t)b * NPTS + pid) * 3 + c] - refs[(size_t)(ref0 + q) * 3 + c]) * 5.0f;
        } else {
            val = features[((size_t)b * NPTS + pid) * 128 + (c - 3)];
        }
        __nv_bfloat16 h = __float2bfloat16_rn(val);
        __nv_bfloat16 l = __float2bfloat16_rn(val - __bfloat162float(h));
        A0hi[rr * A0_STR + c] = h;
        A0lo[rr * A0_STR + c] = l;
    }
    __syncthreads();

    int rl = lane >> 2;           // 0..7
    int cl = (lane & 3) * 2;      // 0,2,4,6

    // ================= layer1: warp w -> rows [16w,16w+16), 8 n-tiles =================
    {
        int r0 = w * 16;
        float d1[8][4];
        #pragma unroll
        for (int ni = 0; ni < 8; ni++)
            #pragma unroll
            for (int e = 0; e < 4; e++) d1[ni][e] = 0.0f;

        for (int ks = 0; ks < 9; ks++) {
            int k0 = ks * 16;
            uint32_t ahi[4], alo[4];
            {
                int r = r0 + rl, c = k0 + cl;
                ahi[0] = *(const uint32_t*)&A0hi[r * A0_STR + c];
                ahi[1] = *(const uint32_t*)&A0hi[(r + 8) * A0_STR + c];
                ahi[2] = *(const uint32_t*)&A0hi[r * A0_STR + c + 8];
                ahi[3] = *(const uint32_t*)&A0hi[(r + 8) * A0_STR + c + 8];
                alo[0] = *(const uint32_t*)&A0lo[r * A0_STR + c];
                alo[1] = *(const uint32_t*)&A0lo[(r + 8) * A0_STR + c];
                alo[2] = *(const uint32_t*)&A0lo[r * A0_STR + c + 8];
                alo[3] = *(const uint32_t*)&A0lo[(r + 8) * A0_STR + c + 8];
            }
            uint32_t bhi[8][2], blo[8][2];
            #pragma unroll
            for (int ni = 0; ni < 8; ni++) {
                int n = ni * 8 + rl, k = k0 + cl;
                bhi[ni][0] = *(const uint32_t*)&B1hi[n * B1_STR + k];
                bhi[ni][1] = *(const uint32_t*)&B1hi[n * B1_STR + k + 8];
                blo[ni][0] = *(const uint32_t*)&B1lo[n * B1_STR + k];
                blo[ni][1] = *(const uint32_t*)&B1lo[n * B1_STR + k + 8];
            }
            #pragma unroll
            for (int ni = 0; ni < 8; ni++) {
                mma_bf16(d1[ni], ahi, bhi[ni]);
                mma_bf16(d1[ni], ahi, blo[ni]);
                mma_bf16(d1[ni], alo, bhi[ni]);
            }
        }
        // epilogue: BN+ReLU -> x1 hi/lo packed u32 stores
        #pragma unroll
        for (int ni = 0; ni < 8; ni++) {
            int col = ni * 8 + cl;
            float s0 = sc1s[col], h0 = sh1s[col];
            float s1 = sc1s[col + 1], h1 = sh1s[col + 1];
            #pragma unroll
            for (int half = 0; half < 2; half++) {
                int r = r0 + rl + half * 8;
                float y0 = fmaxf(fmaf(d1[ni][2 * half + 0], s0, h0), 0.0f);
                float y1 = fmaxf(fmaf(d1[ni][2 * half + 1], s1, h1), 0.0f);
                __nv_bfloat16 hh0 = __float2bfloat16_rn(y0);
                __nv_bfloat16 hh1 = __float2bfloat16_rn(y1);
                __nv_bfloat16 ll0 = __float2bfloat16_rn(y0 - __bfloat162float(hh0));
                __nv_bfloat16 ll1 = __float2bfloat16_rn(y1 - __bfloat162float(hh1));
                *(uint32_t*)&X1hi[r * X1_STR + col] = pack_bf2(hh0, hh1);
                *(uint32_t*)&X1lo[r * X1_STR + col] = pack_bf2(ll0, ll1);
            }
        }
    }
    __syncthreads();

    // ================= layer2: warp -> rows 32*(w>>1), col half 64*(w&1) =================
    {
        int r0 = (w >> 1) * 32;
        int c0 = (w & 1) * 64;
        float d2[2][8][4];
        #pragma unroll
        for (int mi = 0; mi < 2; mi++)
            #pragma unroll
            for (int ni = 0; ni < 8; ni++)
                #pragma unroll
                for (int e = 0; e < 4; e++) d2[mi][ni][e] = 0.0f;

        for (int ks = 0; ks < 4; ks++) {
            int k0 = ks * 16;
            uint32_t ahi[2][4], alo[2][4];
            #pragma unroll
            for (int mi = 0; mi < 2; mi++) {
                int r = r0 + mi * 16 + rl, c = k0 + cl;
                ahi[mi][0] = *(const uint32_t*)&X1hi[r * X1_STR + c];
                ahi[mi][1] = *(const uint32_t*)&X1hi[(r + 8) * X1_STR + c];
                ahi[mi][2] = *(const uint32_t*)&X1hi[r * X1_STR + c + 8];
                ahi[mi][3] = *(const uint32_t*)&X1hi[(r + 8) * X1_STR + c + 8];
                alo[mi][0] = *(const uint32_t*)&X1lo[r * X1_STR + c];
                alo[mi][1] = *(const uint32_t*)&X1lo[(r + 8) * X1_STR + c];
                alo[mi][2] = *(const uint32_t*)&X1lo[r * X1_STR + c + 8];
                alo[mi][3] = *(const uint32_t*)&X1lo[(r + 8) * X1_STR + c + 8];
            }
            uint32_t bhi[8][2], blo[8][2];
            #pragma unroll
            for (int ni = 0; ni < 8; ni++) {
                int n = c0 + ni * 8 + rl, k = k0 + cl;
                bhi[ni][0] = *(const uint32_t*)&B2hi[n * B2_STR + k];
                bhi[ni][1] = *(const uint32_t*)&B2hi[n * B2_STR + k + 8];
                blo[ni][0] = *(const uint32_t*)&B2lo[n * B2_STR + k];
                blo[ni][1] = *(const uint32_t*)&B2lo[n * B2_STR + k + 8];
            }
            #pragma unroll
            for (int mi = 0; mi < 2; mi++)
                #pragma unroll
                for (int ni = 0; ni < 8; ni++) {
                    mma_bf16(d2[mi][ni], ahi[mi], bhi[ni]);
                    mma_bf16(d2[mi][ni], ahi[mi], blo[ni]);
                    mma_bf16(d2[mi][ni], alo[mi], bhi[ni]);
                }
        }
        // epilogue: BN+ReLU -> g_x2 fp32 (float2 stores)
        #pragma unroll
        for (int mi = 0; mi < 2; mi++)
            #pragma unroll
            for (int ni = 0; ni < 8; ni++) {
                int col = c0 + ni * 8 + cl;
                float s0 = sc2s[col], h0 = sh2s[col];
                float s1 = sc2s[col + 1], h1 = sh2s[col + 1];
                #pragma unroll
                for (int half = 0; half < 2; half++) {
                    int r = r0 + mi * 16 + rl + half * 8;
                    float y0 = fmaxf(fmaf(d2[mi][ni][2 * half + 0], s0, h0), 0.0f);
                    float y1 = fmaxf(fmaf(d2[mi][ni][2 * half + 1], s1, h1), 0.0f);
                    *(float2*)&g_x2[((size_t)g * 128 + r) * 128 + col] = make_float2(y0, y1);
                }
            }
    }
}

// =====================================================================
// Kernel 3: layer3 via mma.sync bf16 3-pass split + fused BN/ReLU/max.
// (unchanged from R8; passing)
// =====================================================================
#define BF_STRIDE 136
#define S3B_AHI 0
#define S3B_ALO (S3B_AHI + 128*BF_STRIDE*2)
#define S3B_BHI (S3B_ALO + 128*BF_STRIDE*2)
#define S3B_BLO (S3B_BHI + 128*BF_STRIDE*2)
#define S3B_SC  (S3B_BLO + 128*BF_STRIDE*2)
#define S3B_SH  (S3B_SC + 128*4)
#define S3B_TOTAL (S3B_SH + 128*4)

__global__ __launch_bounds__(256) void mlp3_mma_kernel(
    const float* __restrict__ W3, const float* __restrict__ g3,
    const float* __restrict__ b3, const float* __restrict__ m3,
    const float* __restrict__ v3, float* __restrict__ out)
{
    extern __shared__ char smc[];
    __nv_bfloat16* Ahi = (__nv_bfloat16*)(smc + S3B_AHI);
    __nv_bfloat16* Alo = (__nv_bfloat16*)(smc + S3B_ALO);
    __nv_bfloat16* Bhi = (__nv_bfloat16*)(smc + S3B_BHI);
    __nv_bfloat16* Blo = (__nv_bfloat16*)(smc + S3B_BLO);
    float* scs = (float*)(smc + S3B_SC);
    float* shs = (float*)(smc + S3B_SH);

    int t = threadIdx.x;
    int lane = t & 31, wid = t >> 5;
    int g = blockIdx.x;
    int colbase = blockIdx.y * 128;

    if (t < 128) {
        int j = colbase + t;
        float s = g3[j] * rsqrtf(v3[j] + 1e-5f);
        scs[t] = s;
        shs[t] = b3[j] - m3[j] * s;
    }

    for (int e = t; e < 128 * 32; e += 256) {
        int row = e >> 5;
        int k4 = (e & 31) << 2;
        float4 v = *(const float4*)&g_x2[((size_t)g * 128 + row) * 128 + k4];
        float vv[4] = {v.x, v.y, v.z, v.w};
        #pragma unroll
        for (int j = 0; j < 4; j++) {
            __nv_bfloat16 h = __float2bfloat16_rn(vv[j]);
            __nv_bfloat16 l = __float2bfloat16_rn(vv[j] - __bfloat162float(h));
            Ahi[row * BF_STRIDE + k4 + j] = h;
            Alo[row * BF_STRIDE + k4 + j] = l;
        }
    }
    for (int e = t; e < 128 * 128; e += 256) {
        int k = e >> 7, n = e & 127;
        float w = W3[k * 256 + colbase + n];
        __nv_bfloat16 h = __float2bfloat16_rn(w);
        __nv_bfloat16 l = __float2bfloat16_rn(w - __bfloat162float(h));
        Bhi[n * BF_STRIDE + k] = h;
        Blo[n * BF_STRIDE + k] = l;
    }
    __syncthreads();

    int r0 = (wid >> 1) * 32;
    int c0 = (wid & 1) * 64;
    int q  = wid >> 1;

    float d[2][8][4];
    #pragma unroll
    for (int mi = 0; mi < 2; mi++)
        #pragma unroll
        for (int ni = 0; ni < 8; ni++)
            #pragma unroll
            for (int e = 0; e < 4; e++) d[mi][ni][e] = 0.0f;

    int rl = lane >> 2;
    int cl = (lane & 3) * 2;

    for (int ks = 0; ks < 8; ks++) {
        int k0 = ks * 16;
        uint32_t ahi[2][4], alo[2][4];
        #pragma unroll
        for (int mi = 0; mi < 2; mi++) {
            int r = r0 + mi * 16 + rl;
            int c = k0 + cl;
            ahi[mi][0] = *(const uint32_t*)&Ahi[r * BF_STRIDE + c];
            ahi[mi][1] = *(const uint32_t*)&Ahi[(r + 8) * BF_STRIDE + c];
            ahi[mi][2] = *(const uint32_t*)&Ahi[r * BF_STRIDE + c + 8];
            ahi[mi][3] = *(const uint32_t*)&Ahi[(r + 8) * BF_STRIDE + c + 8];
            alo[mi][0] = *(const uint32_t*)&Alo[r * BF_STRIDE + c];
            alo[mi][1] = *(const uint32_t*)&Alo[(r + 8) * BF_STRIDE + c];
            alo[mi][2] = *(const uint32_t*)&Alo[r * BF_STRIDE + c + 8];
            alo[mi][3] = *(const uint32_t*)&Alo[(r + 8) * BF_STRIDE + c + 8];
        }
        uint32_t bhi[8][2], blo[8][2];
        #pragma unroll
        for (int ni = 0; ni < 8; ni++) {
            int n = c0 + ni * 8 + rl;
            int k = k0 + cl;
            bhi[ni][0] = *(const uint32_t*)&Bhi[n * BF_STRIDE + k];
            bhi[ni][1] = *(const uint32_t*)&Bhi[n * BF_STRIDE + k + 8];
            blo[ni][0] = *(const uint32_t*)&Blo[n * BF_STRIDE + k];
            blo[ni][1] = *(const uint32_t*)&Blo[n * BF_STRIDE + k + 8];
        }
        #pragma unroll
        for (int mi = 0; mi < 2; mi++)
            #pragma unroll
            for (int ni = 0; ni < 8; ni++) {
                mma_bf16(d[mi][ni], ahi[mi], bhi[ni]);
                mma_bf16(d[mi][ni], ahi[mi], blo[ni]);
                mma_bf16(d[mi][ni], alo[mi], bhi[ni]);
            }
    }

    #pragma unroll
    for (int ni = 0; ni < 8; ni++) {
        #pragma unroll
        for (int e = 0; e < 2; e++) {
            int col = c0 + ni * 8 + cl + e;
            float s = scs[col], h = shs[col];
            float mx = 0.0f;
            #pragma unroll
            for (int mi = 0; mi < 2; mi++) {
                mx = fmaxf(mx, fmaxf(fmaf(d[mi][ni][e],     s, h), 0.0f));
                mx = fmaxf(mx, fmaxf(fmaf(d[mi][ni][2 + e], s, h), 0.0f));
            }
            mx = fmaxf(mx, __shfl_xor_sync(0xffffffffu, mx, 4));
            mx = fmaxf(mx, __shfl_xor_sync(0xffffffffu, mx, 8));
            mx = fmaxf(mx, __shfl_xor_sync(0xffffffffu, mx, 16));
            if (lane < 4)
                out[((size_t)g * 4 + q) * 256 + colbase + col] = mx;
        }
    }
}

// =====================================================================
extern "C" void kernel_launch(void* const* d_in, const int* in_sizes, int n_in,
                              void* d_out, int out_size)
{
    const float* points   = (const float*)d_in[0];
    const float* features = (const float*)d_in[1];
    const float* refs     = (const float*)d_in[2];
    const float* W1 = (const float*)d_in[3];
    const float* g1 = (const float*)d_in[4];
    const float* b1 = (const float*)d_in[5];
    const float* m1 = (const float*)d_in[6];
    const float* v1 = (const float*)d_in[7];
    const float* W2 = (const float*)d_in[8];
    const float* g2 = (const float*)d_in[9];
    const float* b2 = (const float*)d_in[10];
    const float* m2 = (const float*)d_in[11];
    const float* v2 = (const float*)d_in[12];
    const float* W3 = (const float*)d_in[13];
    const float* g3 = (const float*)d_in[14];
    const float* b3 = (const float*)d_in[15];
    const float* m3 = (const float*)d_in[16];
    const float* v3 = (const float*)d_in[17];
    float* out = (float*)d_out;

    cudaFuncSetAttribute(mlp12_mma_kernel, cudaFuncAttributeMaxDynamicSharedMemorySize, SB_TOT);
    cudaFuncSetAttribute(mlp3_mma_kernel,  cudaFuncAttributeMaxDynamicSharedMemorySize, S3B_TOTAL);

    ball_query_kernel<<<NREF / 8, 256>>>(points, refs);
    mlp12_mma_kernel<<<NREF / 4, 256, SB_TOT>>>(points, features, refs,
                                                W1, g1, b1, m1, v1,
                                                W2, g2, b2, m2, v2);
    mlp3_mma_kernel<<<dim3(NREF / 4, 2), 256, S3B_TOTAL>>>(W3, g3, b3, m3, v3, out);
}

// round 12
// speedup vs baseline: 2.7551x; 1.8185x over previous
#include <cuda_runtime.h>
#include <cuda_bf16.h>
#include <math.h>
#include <stdint.h>

#define BATCH 4
#define NPTS 20000
#define NS 1024
#define NC 128
#define NK 32
#define NREF (BATCH * NS)   // 4096

// ---------------- scratch (static device globals; no allocations) ----------------
__device__ int   g_idx[NREF * NK];                                   // 512 KB
__device__ __align__(16) __nv_bfloat16 g_x2hi[(size_t)NREF * NK * 128];  // 32 MB
__device__ __align__(16) __nv_bfloat16 g_x2lo[(size_t)NREF * NK * 128];  // 32 MB
// pre-converted weights (hi/lo bf16, n-major, padded/zero-filled K)
__device__ __align__(16) __nv_bfloat16 g_b1hi[64 * 152], g_b1lo[64 * 152];
__device__ __align__(16) __nv_bfloat16 g_b2hi[128 * 72], g_b2lo[128 * 72];
__device__ __align__(16) __nv_bfloat16 g_w3hi[256 * 136], g_w3lo[256 * 136];
__device__ float g_sc1[64], g_sh1[64], g_sc2[128], g_sh2[128], g_sc3[256], g_sh3[256];

__device__ __forceinline__ void split_bf(float v, __nv_bfloat16& h, __nv_bfloat16& l) {
    h = __float2bfloat16_rn(v);
    l = __float2bfloat16_rn(v - __bfloat162float(h));
}
__device__ __forceinline__ uint32_t pack_bf2(__nv_bfloat16 a, __nv_bfloat16 b) {
    uint16_t ua = *(uint16_t*)&a, ub = *(uint16_t*)&b;
    return (uint32_t)ua | ((uint32_t)ub << 16);
}
__device__ __forceinline__ void pack_hl2(float a, float b, uint32_t& hi, uint32_t& lo) {
    __nv_bfloat16 ha, la, hb, lb;
    split_bf(a, ha, la); split_bf(b, hb, lb);
    hi = pack_bf2(ha, hb); lo = pack_bf2(la, lb);
}
__device__ __forceinline__ void mma_bf16(float* d, const uint32_t* a, const uint32_t* b) {
    asm volatile(
        "mma.sync.aligned.m16n8k16.row.col.f32.bf16.bf16.f32 "
        "{%0,%1,%2,%3}, {%4,%5,%6,%7}, {%8,%9}, {%0,%1,%2,%3};"
        : "+f"(d[0]), "+f"(d[1]), "+f"(d[2]), "+f"(d[3])
        : "r"(a[0]), "r"(a[1]), "r"(a[2]), "r"(a[3]), "r"(b[0]), "r"(b[1]));
}

// =====================================================================
// Kernel 0: prep — convert weights + BN coeffs once per launch.
// =====================================================================
__global__ __launch_bounds__(256) void prep_kernel(
    const float* __restrict__ W1, const float* __restrict__ W2, const float* __restrict__ W3,
    const float* __restrict__ g1, const float* __restrict__ b1,
    const float* __restrict__ m1, const float* __restrict__ v1,
    const float* __restrict__ g2, const float* __restrict__ b2,
    const float* __restrict__ m2, const float* __restrict__ v2,
    const float* __restrict__ g3, const float* __restrict__ b3,
    const float* __restrict__ m3, const float* __restrict__ v3)
{
    int tid = blockIdx.x * 256 + threadIdx.x;
    int stride = gridDim.x * 256;
    for (int i = tid; i < 64 * 152; i += stride) {
        int n = i / 152, k = i - n * 152;
        float wv = (k < 131) ? W1[k * 64 + n] : 0.0f;
        __nv_bfloat16 h, l; split_bf(wv, h, l);
        g_b1hi[i] = h; g_b1lo[i] = l;
    }
    for (int i = tid; i < 128 * 72; i += stride) {
        int n = i / 72, k = i - n * 72;
        float wv = (k < 64) ? W2[k * 128 + n] : 0.0f;
        __nv_bfloat16 h, l; split_bf(wv, h, l);
        g_b2hi[i] = h; g_b2lo[i] = l;
    }
    for (int i = tid; i < 256 * 136; i += stride) {
        int n = i / 136, k = i - n * 136;
        float wv = (k < 128) ? W3[k * 256 + n] : 0.0f;
        __nv_bfloat16 h, l; split_bf(wv, h, l);
        g_w3hi[i] = h; g_w3lo[i] = l;
    }
    if (tid < 64) {
        float s = g1[tid] * rsqrtf(v1[tid] + 1e-5f);
        g_sc1[tid] = s; g_sh1[tid] = b1[tid] - m1[tid] * s;
    } else if (tid < 192) {
        int j = tid - 64;
        float s = g2[j] * rsqrtf(v2[j] + 1e-5f);
        g_sc2[j] = s; g_sh2[j] = b2[j] - m2[j] * s;
    } else if (tid < 448) {
        int j = tid - 192;
        float s = g3[j] * rsqrtf(v3[j] + 1e-5f);
        g_sc3[j] = s; g_sh3[j] = b3[j] - m3[j] * s;
    }
}

// =====================================================================
// Kernel 1: ball query (unchanged; ~29us measured).
// =====================================================================
__global__ __launch_bounds__(256) void ball_query_kernel(
    const float* __restrict__ points, const float* __restrict__ refs)
{
    int warp = (blockIdx.x * 256 + threadIdx.x) >> 5;
    int lane = threadIdx.x & 31;
    if (warp >= NREF) return;
    int b = warp >> 10;
    const float* rp = refs + (size_t)warp * 3;
    float rx = rp[0], ry = rp[1], rz = rp[2];
    float rr2 = rx * rx + ry * ry + rz * rz;
    const float R2 = 0.2f * 0.2f;
    int* out = g_idx + warp * NK;
    const float* pbase = points + (size_t)b * NPTS * 3;

    int count = 0;
    int first = -1;
    for (int base = 0; base < NPTS && count < NK; base += 128) {
        float px[4], py[4], pz[4];
        #pragma unroll
        for (int j = 0; j < 4; j++) {
            int i = base + j * 32 + lane;
            bool valid = (i < NPTS);
            int ii = valid ? i : 0;
            px[j] = pbase[ii * 3 + 0];
            py[j] = pbase[ii * 3 + 1];
            pz[j] = pbase[ii * 3 + 2];
            if (!valid) { px[j] = 1e9f; }
        }
        #pragma unroll
        for (int j = 0; j < 4; j++) {
            int i = base + j * 32 + lane;
            float pp2 = px[j] * px[j] + py[j] * py[j] + pz[j] * pz[j];
            float dot = rx * px[j] + ry * py[j] + rz * pz[j];
            float d2 = rr2 + pp2 - 2.0f * dot;
            bool pred = d2 < R2;
            unsigned m = __ballot_sync(0xffffffffu, pred);
            if (m) {
                if (first < 0) first = __shfl_sync(0xffffffffu, i, __ffs(m) - 1);
                if (pred) {
                    int rank = __popc(m & ((1u << lane) - 1u));
                    int slot = count + rank;
                    if (slot < NK) out[slot] = i;
                }
                count += __popc(m);
            }
        }
    }
    if (count < NK) {
        int fill = (count == 0) ? (NPTS - 1) : first;
        if (lane >= count) out[lane] = fill;
    }
}

// =====================================================================
// Kernel 2: fused layer1+layer2, register-direct A gather, no x0/x1 smem.
// Block = 4 refs = 128 rows, 256 thr (8 warps). Warp w: rows [16w,16w+16).
// smem: only weight tiles (copied from prep'd globals) + coeffs = 77KB.
// =====================================================================
#define B1_STR 152
#define B2_STR 72
#define SB12_B1HI 0
#define SB12_B1LO (SB12_B1HI + 64*B1_STR*2)    // 19456
#define SB12_B2HI (SB12_B1LO + 64*B1_STR*2)    // 38912
#define SB12_B2LO (SB12_B2HI + 128*B2_STR*2)   // 57344
#define SB12_SC1  (SB12_B2LO + 128*B2_STR*2)   // 75776
#define SB12_SH1  (SB12_SC1 + 64*4)
#define SB12_SC2  (SB12_SH1 + 64*4)
#define SB12_SH2  (SB12_SC2 + 128*4)
#define SB12_TOT  (SB12_SH2 + 128*4)           // 77312

__global__ __launch_bounds__(256, 2) void mlp12_mma_kernel(
    const float* __restrict__ points, const float* __restrict__ features,
    const float* __restrict__ refs)
{
    extern __shared__ char smc[];
    __nv_bfloat16* B1hi = (__nv_bfloat16*)(smc + SB12_B1HI);
    __nv_bfloat16* B1lo = (__nv_bfloat16*)(smc + SB12_B1LO);
    __nv_bfloat16* B2hi = (__nv_bfloat16*)(smc + SB12_B2HI);
    __nv_bfloat16* B2lo = (__nv_bfloat16*)(smc + SB12_B2LO);
    float* sc1s = (float*)(smc + SB12_SC1);
    float* sh1s = (float*)(smc + SB12_SH1);
    float* sc2s = (float*)(smc + SB12_SC2);
    float* sh2s = (float*)(smc + SB12_SH2);

    int t = threadIdx.x;
    int lane = t & 31, w = t >> 5;
    int g = blockIdx.x;
    int ref0 = g * 4;
    int b = ref0 >> 10;

    // ---- stage weights: pure uint4 copies ----
    {
        uint4* d1h = (uint4*)B1hi; const uint4* s1h = (const uint4*)g_b1hi;
        uint4* d1l = (uint4*)B1lo; const uint4* s1l = (const uint4*)g_b1lo;
        for (int e = t; e < 1216; e += 256) { d1h[e] = s1h[e]; d1l[e] = s1l[e]; }
        uint4* d2h = (uint4*)B2hi; const uint4* s2h = (const uint4*)g_b2hi;
        uint4* d2l = (uint4*)B2lo; const uint4* s2l = (const uint4*)g_b2lo;
        for (int e = t; e < 1152; e += 256) { d2h[e] = s2h[e]; d2l[e] = s2l[e]; }
        if (t < 64) { sc1s[t] = g_sc1[t]; sh1s[t] = g_sh1[t]; }
        if (t < 128) { sc2s[t] = g_sc2[t]; sh2s[t] = g_sh2[t]; }
    }
    __syncthreads();

    int rl = lane >> 2;           // 0..7
    int cl = (lane & 3) * 2;      // 0,2,4,6

    // per-thread rows
    int q = w >> 1;
    int ridx = ref0 + q;
    int rA = 16 * w + rl;
    int rB = rA + 8;
    int pidA = g_idx[ridx * NK + (rA & 31)];
    int pidB = g_idx[ridx * NK + (rB & 31)];
    const float* fA = features + ((size_t)b * NPTS + pidA) * 128;
    const float* fB = features + ((size_t)b * NPTS + pidB) * 128;
    float pA0, pA1, pA2, pB0, pB1, pB2;
    {
        const float* pa = points + ((size_t)b * NPTS + pidA) * 3;
        const float* pb = points + ((size_t)b * NPTS + pidB) * 3;
        const float* rr = refs + (size_t)ridx * 3;
        float r0v = rr[0], r1v = rr[1], r2v = rr[2];
        pA0 = (pa[0] - r0v) * 5.0f; pA1 = (pa[1] - r1v) * 5.0f; pA2 = (pa[2] - r2v) * 5.0f;
        pB0 = (pb[0] - r0v) * 5.0f; pB1 = (pb[1] - r1v) * 5.0f; pB2 = (pb[2] - r2v) * 5.0f;
    }

    // ================= layer1: d1[8][4], A from registers =================
    float d1[8][4];
    #pragma unroll
    for (int ni = 0; ni < 8; ni++)
        #pragma unroll
        for (int e = 0; e < 4; e++) d1[ni][e] = 0.0f;

    #pragma unroll
    for (int ks = 0; ks < 9; ks++) {
        int c = 16 * ks + cl;
        float vA0, vA1, vA8, vA9, vB0v, vB1v, vB8, vB9;
        if (ks == 0) {
            if (cl == 0)      { vA0 = pA0;      vA1 = pA1;      vB0v = pB0;      vB1v = pB1; }
            else if (cl == 2) { vA0 = pA2;      vA1 = fA[0];    vB0v = pB2;      vB1v = fB[0]; }
            else              { vA0 = fA[cl-3]; vA1 = fA[cl-2]; vB0v = fB[cl-3]; vB1v = fB[cl-2]; }
            vA8 = fA[cl + 5]; vA9 = fA[cl + 6];
            vB8 = fB[cl + 5]; vB9 = fB[cl + 6];
        } else if (ks == 8) {
            if (cl == 0)      { vA0 = fA[125]; vA1 = fA[126]; vB0v = fB[125]; vB1v = fB[126]; }
            else if (cl == 2) { vA0 = fA[127]; vA1 = 0.0f;    vB0v = fB[127]; vB1v = 0.0f; }
            else              { vA0 = 0.0f;    vA1 = 0.0f;    vB0v = 0.0f;    vB1v = 0.0f; }
            vA8 = 0.0f; vA9 = 0.0f; vB8 = 0.0f; vB9 = 0.0f;
        } else {
            vA0 = fA[c - 3]; vA1 = fA[c - 2]; vA8 = fA[c + 5]; vA9 = fA[c + 6];
            vB0v = fB[c - 3]; vB1v = fB[c - 2]; vB8 = fB[c + 5]; vB9 = fB[c + 6];
        }
        uint32_t ahi[4], alo[4];
        pack_hl2(vA0, vA1, ahi[0], alo[0]);
        pack_hl2(vB0v, vB1v, ahi[1], alo[1]);
        pack_hl2(vA8, vA9, ahi[2], alo[2]);
        pack_hl2(vB8, vB9, ahi[3], alo[3]);

        int k0 = 16 * ks;
        #pragma unroll
        for (int ni = 0; ni < 8; ni++) {
            int n = ni * 8 + rl, k = k0 + cl;
            uint32_t bh[2], bl[2];
            bh[0] = *(const uint32_t*)&B1hi[n * B1_STR + k];
            bh[1] = *(const uint32_t*)&B1hi[n * B1_STR + k + 8];
            bl[0] = *(const uint32_t*)&B1lo[n * B1_STR + k];
            bl[1] = *(const uint32_t*)&B1lo[n * B1_STR + k + 8];
            mma_bf16(d1[ni], ahi, bh);
            mma_bf16(d1[ni], ahi, bl);
            mma_bf16(d1[ni], alo, bh);
        }
    }

    // ---- repack: BN+ReLU(d1) -> layer2 A-fragments (hi/lo), in registers ----
    uint32_t a2hi[4][4], a2lo[4][4];
    #pragma unroll
    for (int kb = 0; kb < 4; kb++) {
        int colL = 16 * kb + cl;         // tile 2kb cols
        int colR = colL + 8;             // tile 2kb+1 cols
        float sL0 = sc1s[colL], hL0 = sh1s[colL], sL1 = sc1s[colL + 1], hL1 = sh1s[colL + 1];
        float sR0 = sc1s[colR], hR0 = sh1s[colR], sR1 = sc1s[colR + 1], hR1 = sh1s[colR + 1];
        float y0 = fmaxf(fmaf(d1[2 * kb][0], sL0, hL0), 0.0f);
        float y1 = fmaxf(fmaf(d1[2 * kb][1], sL1, hL1), 0.0f);
        float y2 = fmaxf(fmaf(d1[2 * kb][2], sL0, hL0), 0.0f);
        float y3 = fmaxf(fmaf(d1[2 * kb][3], sL1, hL1), 0.0f);
        float u0 = fmaxf(fmaf(d1[2 * kb + 1][0], sR0, hR0), 0.0f);
        float u1 = fmaxf(fmaf(d1[2 * kb + 1][1], sR1, hR1), 0.0f);
        float u2 = fmaxf(fmaf(d1[2 * kb + 1][2], sR0, hR0), 0.0f);
        float u3 = fmaxf(fmaf(d1[2 * kb + 1][3], sR1, hR1), 0.0f);
        pack_hl2(y0, y1, a2hi[kb][0], a2lo[kb][0]);
        pack_hl2(y2, y3, a2hi[kb][1], a2lo[kb][1]);
        pack_hl2(u0, u1, a2hi[kb][2], a2lo[kb][2]);
        pack_hl2(u2, u3, a2hi[kb][3], a2lo[kb][3]);
    }

    // ================= layer2: rows 16w..16w+16, all 128 cols, two halves =================
    #pragma unroll
    for (int h = 0; h < 2; h++) {
        float d2[8][4];
        #pragma unroll
        for (int ni = 0; ni < 8; ni++)
            #pragma unroll
            for (int e = 0; e < 4; e++) d2[ni][e] = 0.0f;

        #pragma unroll
        for (int ks = 0; ks < 4; ks++) {
            int k = 16 * ks + cl;
            #pragma unroll
            for (int ni = 0; ni < 8; ni++) {
                int n = 64 * h + ni * 8 + rl;
                uint32_t bh[2], bl[2];
                bh[0] = *(const uint32_t*)&B2hi[n * B2_STR + k];
                bh[1] = *(const uint32_t*)&B2hi[n * B2_STR + k + 8];
                bl[0] = *(const uint32_t*)&B2lo[n * B2_STR + k];
                bl[1] = *(const uint32_t*)&B2lo[n * B2_STR + k + 8];
                mma_bf16(d2[ni], a2hi[ks], bh);
                mma_bf16(d2[ni], a2hi[ks], bl);
                mma_bf16(d2[ni], a2lo[ks], bh);
            }
        }
        // epilogue: BN+ReLU -> g_x2hi/lo packed u32 stores
        #pragma unroll
        for (int ni = 0; ni < 8; ni++) {
            int col = 64 * h + ni * 8 + cl;
            float s0 = sc2s[col], h0 = sh2s[col];
            float s1 = sc2s[col + 1], h1 = sh2s[col + 1];
            float yA0 = fmaxf(fmaf(d2[ni][0], s0, h0), 0.0f);
            float yA1 = fmaxf(fmaf(d2[ni][1], s1, h1), 0.0f);
            float yB0 = fmaxf(fmaf(d2[ni][2], s0, h0), 0.0f);
            float yB1 = fmaxf(fmaf(d2[ni][3], s1, h1), 0.0f);
            uint32_t hA, lA, hB, lB;
            pack_hl2(yA0, yA1, hA, lA);
            pack_hl2(yB0, yB1, hB, lB);
            size_t rowA = (size_t)g * 128 + rA;
            size_t rowB = (size_t)g * 128 + rB;
            *(uint32_t*)&g_x2hi[rowA * 128 + col] = hA;
            *(uint32_t*)&g_x2lo[rowA * 128 + col] = lA;
            *(uint32_t*)&g_x2hi[rowB * 128 + col] = hB;
            *(uint32_t*)&g_x2lo[rowB * 128 + col] = lB;
        }
    }
}

// =====================================================================
// Kernel 3: layer3 — staging is now pure copies; mainloop unchanged.
// =====================================================================
#define BF_STRIDE 136
#define S3B_AHI 0
#define S3B_ALO (S3B_AHI + 128*BF_STRIDE*2)
#define S3B_BHI (S3B_ALO + 128*BF_STRIDE*2)
#define S3B_BLO (S3B_BHI + 128*BF_STRIDE*2)
#define S3B_SC  (S3B_BLO + 128*BF_STRIDE*2)
#define S3B_SH  (S3B_SC + 128*4)
#define S3B_TOTAL (S3B_SH + 128*4)

__global__ __launch_bounds__(256) void mlp3_mma_kernel(float* __restrict__ out)
{
    extern __shared__ char smc[];
    __nv_bfloat16* Ahi = (__nv_bfloat16*)(smc + S3B_AHI);
    __nv_bfloat16* Alo = (__nv_bfloat16*)(smc + S3B_ALO);
    __nv_bfloat16* Bhi = (__nv_bfloat16*)(smc + S3B_BHI);
    __nv_bfloat16* Blo = (__nv_bfloat16*)(smc + S3B_BLO);
    float* scs = (float*)(smc + S3B_SC);
    float* shs = (float*)(smc + S3B_SH);

    int t = threadIdx.x;
    int lane = t & 31, wid = t >> 5;
    int g = blockIdx.x;
    int colbase = blockIdx.y * 128;

    if (t < 128) {
        scs[t] = g_sc3[colbase + t];
        shs[t] = g_sh3[colbase + t];
    }
    // A copy: 128 rows x 128 bf16 (16 uint4/row) into stride-136 smem rows
    {
        const uint4* sh4 = (const uint4*)(g_x2hi + (size_t)g * 128 * 128);
        const uint4* sl4 = (const uint4*)(g_x2lo + (size_t)g * 128 * 128);
        uint4* dh4 = (uint4*)Ahi;
        uint4* dl4 = (uint4*)Alo;
        for (int e = t; e < 128 * 16; e += 256) {
            int row = e >> 4, j = e & 15;
            dh4[row * 17 + j] = sh4[e];
            dl4[row * 17 + j] = sl4[e];
        }
    }
    // B copy: rows colbase..colbase+128 of g_w3 (stride 136 = 17 uint4), contiguous
    {
        const uint4* sh4 = (const uint4*)g_w3hi + colbase * 17;
        const uint4* sl4 = (const uint4*)g_w3lo + colbase * 17;
        uint4* dh4 = (uint4*)Bhi;
        uint4* dl4 = (uint4*)Blo;
        for (int e = t; e < 128 * 17; e += 256) {
            dh4[e] = sh4[e];
            dl4[e] = sl4[e];
        }
    }
    __syncthreads();

    int r0 = (wid >> 1) * 32;
    int c0 = (wid & 1) * 64;
    int q  = wid >> 1;

    float d[2][8][4];
    #pragma unroll
    for (int mi = 0; mi < 2; mi++)
        #pragma unroll
        for (int ni = 0; ni < 8; ni++)
            #pragma unroll
            for (int e = 0; e < 4; e++) d[mi][ni][e] = 0.0f;

    int rl = lane >> 2;
    int cl = (lane & 3) * 2;

    for (int ks = 0; ks < 8; ks++) {
        int k0 = ks * 16;
        uint32_t ahi[2][4], alo[2][4];
        #pragma unroll
        for (int mi = 0; mi < 2; mi++) {
            int r = r0 + mi * 16 + rl;
            int c = k0 + cl;
            ahi[mi][0] = *(const uint32_t*)&Ahi[r * BF_STRIDE + c];
            ahi[mi][1] = *(const uint32_t*)&Ahi[(r + 8) * BF_STRIDE + c];
            ahi[mi][2] = *(const uint32_t*)&Ahi[r * BF_STRIDE + c + 8];
            ahi[mi][3] = *(const uint32_t*)&Ahi[(r + 8) * BF_STRIDE + c + 8];
            alo[mi][0] = *(const uint32_t*)&Alo[r * BF_STRIDE + c];
            alo[mi][1] = *(const uint32_t*)&Alo[(r + 8) * BF_STRIDE + c];
            alo[mi][2] = *(const uint32_t*)&Alo[r * BF_STRIDE + c + 8];
            alo[mi][3] = *(const uint32_t*)&Alo[(r + 8) * BF_STRIDE + c + 8];
        }
        uint32_t bhi[8][2], blo[8][2];
        #pragma unroll
        for (int ni = 0; ni < 8; ni++) {
            int n = c0 + ni * 8 + rl;
            int k = k0 + cl;
            bhi[ni][0] = *(const uint32_t*)&Bhi[n * BF_STRIDE + k];
            bhi[ni][1] = *(const uint32_t*)&Bhi[n * BF_STRIDE + k + 8];
            blo[ni][0] = *(const uint32_t*)&Blo[n * BF_STRIDE + k];
            blo[ni][1] = *(const uint32_t*)&Blo[n * BF_STRIDE + k + 8];
        }
        #pragma unroll
        for (int mi = 0; mi < 2; mi++)
            #pragma unroll
            for (int ni = 0; ni < 8; ni++) {
                mma_bf16(d[mi][ni], ahi[mi], bhi[ni]);
                mma_bf16(d[mi][ni], ahi[mi], blo[ni]);
                mma_bf16(d[mi][ni], alo[mi], bhi[ni]);
            }
    }

    #pragma unroll
    for (int ni = 0; ni < 8; ni++) {
        #pragma unroll
        for (int e = 0; e < 2; e++) {
            int col = c0 + ni * 8 + cl + e;
            float s = scs[col], h = shs[col];
            float mx = 0.0f;
            #pragma unroll
            for (int mi = 0; mi < 2; mi++) {
                mx = fmaxf(mx, fmaxf(fmaf(d[mi][ni][e],     s, h), 0.0f));
                mx = fmaxf(mx, fmaxf(fmaf(d[mi][ni][2 + e], s, h), 0.0f));
            }
            mx = fmaxf(mx, __shfl_xor_sync(0xffffffffu, mx, 4));
            mx = fmaxf(mx, __shfl_xor_sync(0xffffffffu, mx, 8));
            mx = fmaxf(mx, __shfl_xor_sync(0xffffffffu, mx, 16));
            if (lane < 4)
                out[((size_t)g * 4 + q) * 256 + colbase + col] = mx;
        }
    }
}

// =====================================================================
extern "C" void kernel_launch(void* const* d_in, const int* in_sizes, int n_in,
                              void* d_out, int out_size)
{
    const float* points   = (const float*)d_in[0];
    const float* features = (const float*)d_in[1];
    const float* refs     = (const float*)d_in[2];
    const float* W1 = (const float*)d_in[3];
    const float* g1 = (const float*)d_in[4];
    const float* b1 = (const float*)d_in[5];
    const float* m1 = (const float*)d_in[6];
    const float* v1 = (const float*)d_in[7];
    const float* W2 = (const float*)d_in[8];
    const float* g2 = (const float*)d_in[9];
    const float* b2 = (const float*)d_in[10];
    const float* m2 = (const float*)d_in[11];
    const float* v2 = (const float*)d_in[12];
    const float* W3 = (const float*)d_in[13];
    const float* g3 = (const float*)d_in[14];
    const float* b3 = (const float*)d_in[15];
    const float* m3 = (const float*)d_in[16];
    const float* v3 = (const float*)d_in[17];
    float* out = (float*)d_out;

    cudaFuncSetAttribute(mlp12_mma_kernel, cudaFuncAttributeMaxDynamicSharedMemorySize, SB12_TOT);
    cudaFuncSetAttribute(mlp3_mma_kernel,  cudaFuncAttributeMaxDynamicSharedMemorySize, S3B_TOTAL);

    prep_kernel<<<64, 256>>>(W1, W2, W3, g1, b1, m1, v1,
                             g2, b2, m2, v2, g3, b3, m3, v3);
    ball_query_kernel<<<NREF / 8, 256>>>(points, refs);
    mlp12_mma_kernel<<<NREF / 4, 256, SB12_TOT>>>(points, features, refs);
    mlp3_mma_kernel<<<dim3(NREF / 4, 2), 256, S3B_TOTAL>>>(out);
}

// round 14
// speedup vs baseline: 2.9893x; 1.0850x over previous
#include <cuda_runtime.h>
#include <cuda_bf16.h>
#include <math.h>
#include <stdint.h>

#define BATCH 4
#define NPTS 20000
#define NS 1024
#define NC 128
#define NK 32
#define NREF (BATCH * NS)   // 4096

// ---------------- scratch (static device globals; no allocations) ----------------
__device__ int   g_idx[NREF * NK];                                   // 512 KB
__device__ __align__(16) __nv_bfloat16 g_x2hi[(size_t)NREF * NK * 128];  // 32 MB
__device__ __align__(16) __nv_bfloat16 g_x2lo[(size_t)NREF * NK * 128];  // 32 MB
// pre-converted weights (hi/lo bf16, n-major, padded/zero-filled K)
__device__ __align__(16) __nv_bfloat16 g_b1hi[64 * 152], g_b1lo[64 * 152];
__device__ __align__(16) __nv_bfloat16 g_b2hi[128 * 72], g_b2lo[128 * 72];
__device__ __align__(16) __nv_bfloat16 g_w3hi[256 * 136], g_w3lo[256 * 136];
__device__ float g_sc1[64], g_sh1[64], g_sc2[128], g_sh2[128], g_sc3[256], g_sh3[256];

__device__ __forceinline__ void split_bf(float v, __nv_bfloat16& h, __nv_bfloat16& l) {
    h = __float2bfloat16_rn(v);
    l = __float2bfloat16_rn(v - __bfloat162float(h));
}
__device__ __forceinline__ uint32_t pack_bf2(__nv_bfloat16 a, __nv_bfloat16 b) {
    uint16_t ua = *(uint16_t*)&a, ub = *(uint16_t*)&b;
    return (uint32_t)ua | ((uint32_t)ub << 16);
}
__device__ __forceinline__ void pack_hl2(float a, float b, uint32_t& hi, uint32_t& lo) {
    __nv_bfloat16 ha, la, hb, lb;
    split_bf(a, ha, la); split_bf(b, hb, lb);
    hi = pack_bf2(ha, hb); lo = pack_bf2(la, lb);
}
__device__ __forceinline__ void mma_bf16(float* d, const uint32_t* a, const uint32_t* b) {
    asm volatile(
        "mma.sync.aligned.m16n8k16.row.col.f32.bf16.bf16.f32 "
        "{%0,%1,%2,%3}, {%4,%5,%6,%7}, {%8,%9}, {%0,%1,%2,%3};"
        : "+f"(d[0]), "+f"(d[1]), "+f"(d[2]), "+f"(d[3])
        : "r"(a[0]), "r"(a[1]), "r"(a[2]), "r"(a[3]), "r"(b[0]), "r"(b[1]));
}

// =====================================================================
// Kernel 0: prep — convert weights + BN coeffs once per launch.
// =====================================================================
__global__ __launch_bounds__(256) void prep_kernel(
    const float* __restrict__ W1, const float* __restrict__ W2, const float* __restrict__ W3,
    const float* __restrict__ g1, const float* __restrict__ b1,
    const float* __restrict__ m1, const float* __restrict__ v1,
    const float* __restrict__ g2, const float* __restrict__ b2,
    const float* __restrict__ m2, const float* __restrict__ v2,
    const float* __restrict__ g3, const float* __restrict__ b3,
    const float* __restrict__ m3, const float* __restrict__ v3)
{
    int tid = blockIdx.x * 256 + threadIdx.x;
    int stride = gridDim.x * 256;
    for (int i = tid; i < 64 * 152; i += stride) {
        int n = i / 152, k = i - n * 152;
        float wv = (k < 131) ? W1[k * 64 + n] : 0.0f;
        __nv_bfloat16 h, l; split_bf(wv, h, l);
        g_b1hi[i] = h; g_b1lo[i] = l;
    }
    for (int i = tid; i < 128 * 72; i += stride) {
        int n = i / 72, k = i - n * 72;
        float wv = (k < 64) ? W2[k * 128 + n] : 0.0f;
        __nv_bfloat16 h, l; split_bf(wv, h, l);
        g_b2hi[i] = h; g_b2lo[i] = l;
    }
    for (int i = tid; i < 256 * 136; i += stride) {
        int n = i / 136, k = i - n * 136;
        float wv = (k < 128) ? W3[k * 256 + n] : 0.0f;
        __nv_bfloat16 h, l; split_bf(wv, h, l);
        g_w3hi[i] = h; g_w3lo[i] = l;
    }
    if (tid < 64) {
        float s = g1[tid] * rsqrtf(v1[tid] + 1e-5f);
        g_sc1[tid] = s; g_sh1[tid] = b1[tid] - m1[tid] * s;
    } else if (tid < 192) {
        int j = tid - 64;
        float s = g2[j] * rsqrtf(v2[j] + 1e-5f);
        g_sc2[j] = s; g_sh2[j] = b2[j] - m2[j] * s;
    } else if (tid < 448) {
        int j = tid - 192;
        float s = g3[j] * rsqrtf(v3[j] + 1e-5f);
        g_sc3[j] = s; g_sh3[j] = b3[j] - m3[j] * s;
    }
}

// =====================================================================
// Kernel 1: ball query (unchanged; ~29us measured).
// =====================================================================
__global__ __launch_bounds__(256) void ball_query_kernel(
    const float* __restrict__ points, const float* __restrict__ refs)
{
    int warp = (blockIdx.x * 256 + threadIdx.x) >> 5;
    int lane = threadIdx.x & 31;
    if (warp >= NREF) return;
    int b = warp >> 10;
    const float* rp = refs + (size_t)warp * 3;
    float rx = rp[0], ry = rp[1], rz = rp[2];
    float rr2 = rx * rx + ry * ry + rz * rz;
    const float R2 = 0.2f * 0.2f;
    int* out = g_idx + warp * NK;
    const float* pbase = points + (size_t)b * NPTS * 3;

    int count = 0;
    int first = -1;
    for (int base = 0; base < NPTS && count < NK; base += 128) {
        float px[4], py[4], pz[4];
        #pragma unroll
        for (int j = 0; j < 4; j++) {
            int i = base + j * 32 + lane;
            bool valid = (i < NPTS);
            int ii = valid ? i : 0;
            px[j] = pbase[ii * 3 + 0];
            py[j] = pbase[ii * 3 + 1];
            pz[j] = pbase[ii * 3 + 2];
            if (!valid) { px[j] = 1e9f; }
        }
        #pragma unroll
        for (int j = 0; j < 4; j++) {
            int i = base + j * 32 + lane;
            float pp2 = px[j] * px[j] + py[j] * py[j] + pz[j] * pz[j];
            float dot = rx * px[j] + ry * py[j] + rz * pz[j];
            float d2 = rr2 + pp2 - 2.0f * dot;
            bool pred = d2 < R2;
            unsigned m = __ballot_sync(0xffffffffu, pred);
            if (m) {
                if (first < 0) first = __shfl_sync(0xffffffffu, i, __ffs(m) - 1);
                if (pred) {
                    int rank = __popc(m & ((1u << lane) - 1u));
                    int slot = count + rank;
                    if (slot < NK) out[slot] = i;
                }
                count += __popc(m);
            }
        }
    }
    if (count < NK) {
        int fill = (count == 0) ? (NPTS - 1) : first;
        if (lane >= count) out[lane] = fill;
    }
}

// =====================================================================
// Kernel 2: fused layer1+layer2 (unchanged from R12; ~53us measured).
// =====================================================================
#define B1_STR 152
#define B2_STR 72
#define SB12_B1HI 0
#define SB12_B1LO (SB12_B1HI + 64*B1_STR*2)    // 19456
#define SB12_B2HI (SB12_B1LO + 64*B1_STR*2)    // 38912
#define SB12_B2LO (SB12_B2HI + 128*B2_STR*2)   // 57344
#define SB12_SC1  (SB12_B2LO + 128*B2_STR*2)   // 75776
#define SB12_SH1  (SB12_SC1 + 64*4)
#define SB12_SC2  (SB12_SH1 + 64*4)
#define SB12_SH2  (SB12_SC2 + 128*4)
#define SB12_TOT  (SB12_SH2 + 128*4)           // 77312

__global__ __launch_bounds__(256, 2) void mlp12_mma_kernel(
    const float* __restrict__ points, const float* __restrict__ features,
    const float* __restrict__ refs)
{
    extern __shared__ char smc[];
    __nv_bfloat16* B1hi = (__nv_bfloat16*)(smc + SB12_B1HI);
    __nv_bfloat16* B1lo = (__nv_bfloat16*)(smc + SB12_B1LO);
    __nv_bfloat16* B2hi = (__nv_bfloat16*)(smc + SB12_B2HI);
    __nv_bfloat16* B2lo = (__nv_bfloat16*)(smc + SB12_B2LO);
    float* sc1s = (float*)(smc + SB12_SC1);
    float* sh1s = (float*)(smc + SB12_SH1);
    float* sc2s = (float*)(smc + SB12_SC2);
    float* sh2s = (float*)(smc + SB12_SH2);

    int t = threadIdx.x;
    int lane = t & 31, w = t >> 5;
    int g = blockIdx.x;
    int ref0 = g * 4;
    int b = ref0 >> 10;

    // ---- stage weights: pure uint4 copies ----
    {
        uint4* d1h = (uint4*)B1hi; const uint4* s1h = (const uint4*)g_b1hi;
        uint4* d1l = (uint4*)B1lo; const uint4* s1l = (const uint4*)g_b1lo;
        for (int e = t; e < 1216; e += 256) { d1h[e] = s1h[e]; d1l[e] = s1l[e]; }
        uint4* d2h = (uint4*)B2hi; const uint4* s2h = (const uint4*)g_b2hi;
        uint4* d2l = (uint4*)B2lo; const uint4* s2l = (const uint4*)g_b2lo;
        for (int e = t; e < 1152; e += 256) { d2h[e] = s2h[e]; d2l[e] = s2l[e]; }
        if (t < 64) { sc1s[t] = g_sc1[t]; sh1s[t] = g_sh1[t]; }
        if (t < 128) { sc2s[t] = g_sc2[t]; sh2s[t] = g_sh2[t]; }
    }
    __syncthreads();

    int rl = lane >> 2;           // 0..7
    int cl = (lane & 3) * 2;      // 0,2,4,6

    int q = w >> 1;
    int ridx = ref0 + q;
    int rA = 16 * w + rl;
    int rB = rA + 8;
    int pidA = g_idx[ridx * NK + (rA & 31)];
    int pidB = g_idx[ridx * NK + (rB & 31)];
    const float* fA = features + ((size_t)b * NPTS + pidA) * 128;
    const float* fB = features + ((size_t)b * NPTS + pidB) * 128;
    float pA0, pA1, pA2, pB0, pB1, pB2;
    {
        const float* pa = points + ((size_t)b * NPTS + pidA) * 3;
        const float* pb = points + ((size_t)b * NPTS + pidB) * 3;
        const float* rr = refs + (size_t)ridx * 3;
        float r0v = rr[0], r1v = rr[1], r2v = rr[2];
        pA0 = (pa[0] - r0v) * 5.0f; pA1 = (pa[1] - r1v) * 5.0f; pA2 = (pa[2] - r2v) * 5.0f;
        pB0 = (pb[0] - r0v) * 5.0f; pB1 = (pb[1] - r1v) * 5.0f; pB2 = (pb[2] - r2v) * 5.0f;
    }

    float d1[8][4];
    #pragma unroll
    for (int ni = 0; ni < 8; ni++)
        #pragma unroll
        for (int e = 0; e < 4; e++) d1[ni][e] = 0.0f;

    #pragma unroll
    for (int ks = 0; ks < 9; ks++) {
        int c = 16 * ks + cl;
        float vA0, vA1, vA8, vA9, vB0v, vB1v, vB8, vB9;
        if (ks == 0) {
            if (cl == 0)      { vA0 = pA0;      vA1 = pA1;      vB0v = pB0;      vB1v = pB1; }
            else if (cl == 2) { vA0 = pA2;      vA1 = fA[0];    vB0v = pB2;      vB1v = fB[0]; }
            else              { vA0 = fA[cl-3]; vA1 = fA[cl-2]; vB0v = fB[cl-3]; vB1v = fB[cl-2]; }
            vA8 = fA[cl + 5]; vA9 = fA[cl + 6];
            vB8 = fB[cl + 5]; vB9 = fB[cl + 6];
        } else if (ks == 8) {
            if (cl == 0)      { vA0 = fA[125]; vA1 = fA[126]; vB0v = fB[125]; vB1v = fB[126]; }
            else if (cl == 2) { vA0 = fA[127]; vA1 = 0.0f;    vB0v = fB[127]; vB1v = 0.0f; }
            else              { vA0 = 0.0f;    vA1 = 0.0f;    vB0v = 0.0f;    vB1v = 0.0f; }
            vA8 = 0.0f; vA9 = 0.0f; vB8 = 0.0f; vB9 = 0.0f;
        } else {
            vA0 = fA[c - 3]; vA1 = fA[c - 2]; vA8 = fA[c + 5]; vA9 = fA[c + 6];
            vB0v = fB[c - 3]; vB1v = fB[c - 2]; vB8 = fB[c + 5]; vB9 = fB[c + 6];
        }
        uint32_t ahi[4], alo[4];
        pack_hl2(vA0, vA1, ahi[0], alo[0]);
        pack_hl2(vB0v, vB1v, ahi[1], alo[1]);
        pack_hl2(vA8, vA9, ahi[2], alo[2]);
        pack_hl2(vB8, vB9, ahi[3], alo[3]);

        int k0 = 16 * ks;
        #pragma unroll
        for (int ni = 0; ni < 8; ni++) {
            int n = ni * 8 + rl, k = k0 + cl;
            uint32_t bh[2], bl[2];
            bh[0] = *(const uint32_t*)&B1hi[n * B1_STR + k];
            bh[1] = *(const uint32_t*)&B1hi[n * B1_STR + k + 8];
            bl[0] = *(const uint32_t*)&B1lo[n * B1_STR + k];
            bl[1] = *(const uint32_t*)&B1lo[n * B1_STR + k + 8];
            mma_bf16(d1[ni], ahi, bh);
            mma_bf16(d1[ni], ahi, bl);
            mma_bf16(d1[ni], alo, bh);
        }
    }

    uint32_t a2hi[4][4], a2lo[4][4];
    #pragma unroll
    for (int kb = 0; kb < 4; kb++) {
        int colL = 16 * kb + cl;
        int colR = colL + 8;
        float sL0 = sc1s[colL], hL0 = sh1s[colL], sL1 = sc1s[colL + 1], hL1 = sh1s[colL + 1];
        float sR0 = sc1s[colR], hR0 = sh1s[colR], sR1 = sc1s[colR + 1], hR1 = sh1s[colR + 1];
        float y0 = fmaxf(fmaf(d1[2 * kb][0], sL0, hL0), 0.0f);
        float y1 = fmaxf(fmaf(d1[2 * kb][1], sL1, hL1), 0.0f);
        float y2 = fmaxf(fmaf(d1[2 * kb][2], sL0, hL0), 0.0f);
        float y3 = fmaxf(fmaf(d1[2 * kb][3], sL1, hL1), 0.0f);
        float u0 = fmaxf(fmaf(d1[2 * kb + 1][0], sR0, hR0), 0.0f);
        float u1 = fmaxf(fmaf(d1[2 * kb + 1][1], sR1, hR1), 0.0f);
        float u2 = fmaxf(fmaf(d1[2 * kb + 1][2], sR0, hR0), 0.0f);
        float u3 = fmaxf(fmaf(d1[2 * kb + 1][3], sR1, hR1), 0.0f);
        pack_hl2(y0, y1, a2hi[kb][0], a2lo[kb][0]);
        pack_hl2(y2, y3, a2hi[kb][1], a2lo[kb][1]);
        pack_hl2(u0, u1, a2hi[kb][2], a2lo[kb][2]);
        pack_hl2(u2, u3, a2hi[kb][3], a2lo[kb][3]);
    }

    #pragma unroll
    for (int h = 0; h < 2; h++) {
        float d2[8][4];
        #pragma unroll
        for (int ni = 0; ni < 8; ni++)
            #pragma unroll
            for (int e = 0; e < 4; e++) d2[ni][e] = 0.0f;

        #pragma unroll
        for (int ks = 0; ks < 4; ks++) {
            int k = 16 * ks + cl;
            #pragma unroll
            for (int ni = 0; ni < 8; ni++) {
                int n = 64 * h + ni * 8 + rl;
                uint32_t bh[2], bl[2];
                bh[0] = *(const uint32_t*)&B2hi[n * B2_STR + k];
                bh[1] = *(const uint32_t*)&B2hi[n * B2_STR + k + 8];
                bl[0] = *(const uint32_t*)&B2lo[n * B2_STR + k];
                bl[1] = *(const uint32_t*)&B2lo[n * B2_STR + k + 8];
                mma_bf16(d2[ni], a2hi[ks], bh);
                mma_bf16(d2[ni], a2hi[ks], bl);
                mma_bf16(d2[ni], a2lo[ks], bh);
            }
        }
        #pragma unroll
        for (int ni = 0; ni < 8; ni++) {
            int col = 64 * h + ni * 8 + cl;
            float s0 = sc2s[col], h0 = sh2s[col];
            float s1 = sc2s[col + 1], h1 = sh2s[col + 1];
            float yA0 = fmaxf(fmaf(d2[ni][0], s0, h0), 0.0f);
            float yA1 = fmaxf(fmaf(d2[ni][1], s1, h1), 0.0f);
            float yB0 = fmaxf(fmaf(d2[ni][2], s0, h0), 0.0f);
            float yB1 = fmaxf(fmaf(d2[ni][3], s1, h1), 0.0f);
            uint32_t hA, lA, hB, lB;
            pack_hl2(yA0, yA1, hA, lA);
            pack_hl2(yB0, yB1, hB, lB);
            size_t rowA = (size_t)g * 128 + rA;
            size_t rowB = (size_t)g * 128 + rB;
            *(uint32_t*)&g_x2hi[rowA * 128 + col] = hA;
            *(uint32_t*)&g_x2lo[rowA * 128 + col] = lA;
            *(uint32_t*)&g_x2hi[rowB * 128 + col] = hB;
            *(uint32_t*)&g_x2lo[rowB * 128 + col] = lB;
        }
    }
}

// =====================================================================
// Kernel 3: layer3 — A fragments DIRECT FROM GLOBAL (no A smem stage),
// B in smem. smem 70KB -> 2 CTAs/SM (was 140KB -> 1).
// =====================================================================
#define BF_STRIDE 136
#define S3B_BHI 0
#define S3B_BLO (S3B_BHI + 128*BF_STRIDE*2)    // 34816
#define S3B_SC  (S3B_BLO + 128*BF_STRIDE*2)    // 69632
#define S3B_SH  (S3B_SC + 128*4)               // 70144
#define S3B_TOTAL (S3B_SH + 128*4)             // 70656

__global__ __launch_bounds__(256, 2) void mlp3_mma_kernel(float* __restrict__ out)
{
    extern __shared__ char smc[];
    __nv_bfloat16* Bhi = (__nv_bfloat16*)(smc + S3B_BHI);
    __nv_bfloat16* Blo = (__nv_bfloat16*)(smc + S3B_BLO);
    float* scs = (float*)(smc + S3B_SC);
    float* shs = (float*)(smc + S3B_SH);

    int t = threadIdx.x;
    int lane = t & 31, wid = t >> 5;
    int g = blockIdx.x;
    int colbase = blockIdx.y * 128;

    if (t < 128) {
        scs[t] = g_sc3[colbase + t];
        shs[t] = g_sh3[colbase + t];
    }
    // B copy: rows colbase..colbase+128 of g_w3 (stride 136 = 17 uint4), contiguous
    {
        const uint4* sh4 = (const uint4*)g_w3hi + colbase * 17;
        const uint4* sl4 = (const uint4*)g_w3lo + colbase * 17;
        uint4* dh4 = (uint4*)Bhi;
        uint4* dl4 = (uint4*)Blo;
        for (int e = t; e < 128 * 17; e += 256) {
            dh4[e] = sh4[e];
            dl4[e] = sl4[e];
        }
    }
    __syncthreads();

    int r0 = (wid >> 1) * 32;
    int c0 = (wid & 1) * 64;
    int q  = wid >> 1;

    float d[2][8][4];
    #pragma unroll
    for (int mi = 0; mi < 2; mi++)
        #pragma unroll
        for (int ni = 0; ni < 8; ni++)
            #pragma unroll
            for (int e = 0; e < 4; e++) d[mi][ni][e] = 0.0f;

    int rl = lane >> 2;
    int cl = (lane & 3) * 2;

    // base pointers for this thread's A rows (global, bf16 hi/lo pre-packed)
    const __nv_bfloat16* Ahg = g_x2hi + ((size_t)g * 128 + r0 + rl) * 128;
    const __nv_bfloat16* Alg = g_x2lo + ((size_t)g * 128 + r0 + rl) * 128;

    for (int ks = 0; ks < 8; ks++) {
        int k0 = ks * 16;
        int c = k0 + cl;
        uint32_t ahi[2][4], alo[2][4];
        #pragma unroll
        for (int mi = 0; mi < 2; mi++) {
            int roff = mi * 16 * 128;
            ahi[mi][0] = *(const uint32_t*)&Ahg[roff + c];
            ahi[mi][1] = *(const uint32_t*)&Ahg[roff + 8 * 128 + c];
            ahi[mi][2] = *(const uint32_t*)&Ahg[roff + c + 8];
            ahi[mi][3] = *(const uint32_t*)&Ahg[roff + 8 * 128 + c + 8];
            alo[mi][0] = *(const uint32_t*)&Alg[roff + c];
            alo[mi][1] = *(const uint32_t*)&Alg[roff + 8 * 128 + c];
            alo[mi][2] = *(const uint32_t*)&Alg[roff + c + 8];
            alo[mi][3] = *(const uint32_t*)&Alg[roff + 8 * 128 + c + 8];
        }
        uint32_t bhi[8][2], blo[8][2];
        #pragma unroll
        for (int ni = 0; ni < 8; ni++) {
            int n = c0 + ni * 8 + rl;
            int k = k0 + cl;
            bhi[ni][0] = *(const uint32_t*)&Bhi[n * BF_STRIDE + k];
            bhi[ni][1] = *(const uint32_t*)&Bhi[n * BF_STRIDE + k + 8];
            blo[ni][0] = *(const uint32_t*)&Blo[n * BF_STRIDE + k];
            blo[ni][1] = *(const uint32_t*)&Blo[n * BF_STRIDE + k + 8];
        }
        #pragma unroll
        for (int mi = 0; mi < 2; mi++)
            #pragma unroll
            for (int ni = 0; ni < 8; ni++) {
                mma_bf16(d[mi][ni], ahi[mi], bhi[ni]);
                mma_bf16(d[mi][ni], ahi[mi], blo[ni]);
                mma_bf16(d[mi][ni], alo[mi], bhi[ni]);
            }
    }

    #pragma unroll
    for (int ni = 0; ni < 8; ni++) {
        #pragma unroll
        for (int e = 0; e < 2; e++) {
            int col = c0 + ni * 8 + cl + e;
            float s = scs[col], h = shs[col];
            float mx = 0.0f;
            #pragma unroll
            for (int mi = 0; mi < 2; mi++) {
                mx = fmaxf(mx, fmaxf(fmaf(d[mi][ni][e],     s, h), 0.0f));
                mx = fmaxf(mx, fmaxf(fmaf(d[mi][ni][2 + e], s, h), 0.0f));
            }
            mx = fmaxf(mx, __shfl_xor_sync(0xffffffffu, mx, 4));
            mx = fmaxf(mx, __shfl_xor_sync(0xffffffffu, mx, 8));
            mx = fmaxf(mx, __shfl_xor_sync(0xffffffffu, mx, 16));
            if (lane < 4)
                out[((size_t)g * 4 + q) * 256 + colbase + col] = mx;
        }
    }
}

// =====================================================================
extern "C" void kernel_launch(void* const* d_in, const int* in_sizes, int n_in,
                              void* d_out, int out_size)
{
    const float* points   = (const float*)d_in[0];
    const float* features = (const float*)d_in[1];
    const float* refs     = (const float*)d_in[2];
    const float* W1 = (const float*)d_in[3];
    const float* g1 = (const float*)d_in[4];
    const float* b1 = (const float*)d_in[5];
    const float* m1 = (const float*)d_in[6];
    const float* v1 = (const float*)d_in[7];
    const float* W2 = (const float*)d_in[8];
    const float* g2 = (const float*)d_in[9];
    const float* b2 = (const float*)d_in[10];
    const float* m2 = (const float*)d_in[11];
    const float* v2 = (const float*)d_in[12];
    const float* W3 = (const float*)d_in[13];
    const float* g3 = (const float*)d_in[14];
    const float* b3 = (const float*)d_in[15];
    const float* m3 = (const float*)d_in[16];
    const float* v3 = (const float*)d_in[17];
    float* out = (float*)d_out;

    cudaFuncSetAttribute(mlp12_mma_kernel, cudaFuncAttributeMaxDynamicSharedMemorySize, SB12_TOT);
    cudaFuncSetAttribute(mlp3_mma_kernel,  cudaFuncAttributeMaxDynamicSharedMemorySize, S3B_TOTAL);

    prep_kernel<<<64, 256>>>(W1, W2, W3, g1, b1, m1, v1,
                             g2, b2, m2, v2, g3, b3, m3, v3);
    ball_query_kernel<<<NREF / 8, 256>>>(points, refs);
    mlp12_mma_kernel<<<NREF / 4, 256, SB12_TOT>>>(points, features, refs);
    mlp3_mma_kernel<<<dim3(NREF / 4, 2), 256, S3B_TOTAL>>>(out);
}

// round 15
// speedup vs baseline: 4.0787x; 1.3644x over previous
#include <cuda_runtime.h>
#include <cuda_bf16.h>
#include <math.h>
#include <stdint.h>

#define BATCH 4
#define NPTS 20000
#define NS 1024
#define NC 128
#define NK 32
#define NREF (BATCH * NS)   // 4096

// ---------------- scratch (static device globals; no allocations) ----------------
__device__ int   g_idx[NREF * NK];                                   // 512 KB
// x2 in FRAGMENT-MAJOR layout: [group g][mb 0..7][ks 0..7][lane 0..31][4 u32]
// tile idx = (g*8 + mb)*8 + ks ; 128 u32 per tile. 32 MB per plane.
__device__ __align__(16) uint32_t g_x2fhi[(size_t)1024 * 8192];
__device__ __align__(16) uint32_t g_x2flo[(size_t)1024 * 8192];
// pre-converted weights (hi/lo bf16, n-major, padded/zero-filled K)
__device__ __align__(16) __nv_bfloat16 g_b1hi[64 * 152], g_b1lo[64 * 152];
__device__ __align__(16) __nv_bfloat16 g_b2hi[128 * 72], g_b2lo[128 * 72];
__device__ __align__(16) __nv_bfloat16 g_w3hi[256 * 136], g_w3lo[256 * 136];
__device__ float g_sc1[64], g_sh1[64], g_sc2[128], g_sh2[128], g_sc3[256], g_sh3[256];

__device__ __forceinline__ void split_bf(float v, __nv_bfloat16& h, __nv_bfloat16& l) {
    h = __float2bfloat16_rn(v);
    l = __float2bfloat16_rn(v - __bfloat162float(h));
}
__device__ __forceinline__ uint32_t pack_bf2(__nv_bfloat16 a, __nv_bfloat16 b) {
    uint16_t ua = *(uint16_t*)&a, ub = *(uint16_t*)&b;
    return (uint32_t)ua | ((uint32_t)ub << 16);
}
__device__ __forceinline__ void pack_hl2(float a, float b, uint32_t& hi, uint32_t& lo) {
    __nv_bfloat16 ha, la, hb, lb;
    split_bf(a, ha, la); split_bf(b, hb, lb);
    hi = pack_bf2(ha, hb); lo = pack_bf2(la, lb);
}
__device__ __forceinline__ void mma_bf16(float* d, const uint32_t* a, const uint32_t* b) {
    asm volatile(
        "mma.sync.aligned.m16n8k16.row.col.f32.bf16.bf16.f32 "
        "{%0,%1,%2,%3}, {%4,%5,%6,%7}, {%8,%9}, {%0,%1,%2,%3};"
        : "+f"(d[0]), "+f"(d[1]), "+f"(d[2]), "+f"(d[3])
        : "r"(a[0]), "r"(a[1]), "r"(a[2]), "r"(a[3]), "r"(b[0]), "r"(b[1]));
}
__device__ __forceinline__ void ldsm_x4(uint32_t* r, uint32_t addr) {
    asm volatile("ldmatrix.sync.aligned.m8n8.x4.shared.b16 {%0,%1,%2,%3}, [%4];"
                 : "=r"(r[0]), "=r"(r[1]), "=r"(r[2]), "=r"(r[3]) : "r"(addr));
}

// =====================================================================
// Kernel 0: prep — convert weights + BN coeffs once per launch.
// =====================================================================
__global__ __launch_bounds__(256) void prep_kernel(
    const float* __restrict__ W1, const float* __restrict__ W2, const float* __restrict__ W3,
    const float* __restrict__ g1, const float* __restrict__ b1,
    const float* __restrict__ m1, const float* __restrict__ v1,
    const float* __restrict__ g2, const float* __restrict__ b2,
    const float* __restrict__ m2, const float* __restrict__ v2,
    const float* __restrict__ g3, const float* __restrict__ b3,
    const float* __restrict__ m3, const float* __restrict__ v3)
{
    int tid = blockIdx.x * 256 + threadIdx.x;
    int stride = gridDim.x * 256;
    for (int i = tid; i < 64 * 152; i += stride) {
        int n = i / 152, k = i - n * 152;
        float wv = (k < 131) ? W1[k * 64 + n] : 0.0f;
        __nv_bfloat16 h, l; split_bf(wv, h, l);
        g_b1hi[i] = h; g_b1lo[i] = l;
    }
    for (int i = tid; i < 128 * 72; i += stride) {
        int n = i / 72, k = i - n * 72;
        float wv = (k < 64) ? W2[k * 128 + n] : 0.0f;
        __nv_bfloat16 h, l; split_bf(wv, h, l);
        g_b2hi[i] = h; g_b2lo[i] = l;
    }
    for (int i = tid; i < 256 * 136; i += stride) {
        int n = i / 136, k = i - n * 136;
        float wv = (k < 128) ? W3[k * 256 + n] : 0.0f;
        __nv_bfloat16 h, l; split_bf(wv, h, l);
        g_w3hi[i] = h; g_w3lo[i] = l;
    }
    if (tid < 64) {
        float s = g1[tid] * rsqrtf(v1[tid] + 1e-5f);
        g_sc1[tid] = s; g_sh1[tid] = b1[tid] - m1[tid] * s;
    } else if (tid < 192) {
        int j = tid - 64;
        float s = g2[j] * rsqrtf(v2[j] + 1e-5f);
        g_sc2[j] = s; g_sh2[j] = b2[j] - m2[j] * s;
    } else if (tid < 448) {
        int j = tid - 192;
        float s = g3[j] * rsqrtf(v3[j] + 1e-5f);
        g_sc3[j] = s; g_sh3[j] = b3[j] - m3[j] * s;
    }
}

// =====================================================================
// Kernel 1: ball query (unchanged; ~29us measured).
// =====================================================================
__global__ __launch_bounds__(256) void ball_query_kernel(
    const float* __restrict__ points, const float* __restrict__ refs)
{
    int warp = (blockIdx.x * 256 + threadIdx.x) >> 5;
    int lane = threadIdx.x & 31;
    if (warp >= NREF) return;
    int b = warp >> 10;
    const float* rp = refs + (size_t)warp * 3;
    float rx = rp[0], ry = rp[1], rz = rp[2];
    float rr2 = rx * rx + ry * ry + rz * rz;
    const float R2 = 0.2f * 0.2f;
    int* out = g_idx + warp * NK;
    const float* pbase = points + (size_t)b * NPTS * 3;

    int count = 0;
    int first = -1;
    for (int base = 0; base < NPTS && count < NK; base += 128) {
        float px[4], py[4], pz[4];
        #pragma unroll
        for (int j = 0; j < 4; j++) {
            int i = base + j * 32 + lane;
            bool valid = (i < NPTS);
            int ii = valid ? i : 0;
            px[j] = pbase[ii * 3 + 0];
            py[j] = pbase[ii * 3 + 1];
            pz[j] = pbase[ii * 3 + 2];
            if (!valid) { px[j] = 1e9f; }
        }
        #pragma unroll
        for (int j = 0; j < 4; j++) {
            int i = base + j * 32 + lane;
            float pp2 = px[j] * px[j] + py[j] * py[j] + pz[j] * pz[j];
            float dot = rx * px[j] + ry * py[j] + rz * pz[j];
            float d2 = rr2 + pp2 - 2.0f * dot;
            bool pred = d2 < R2;
            unsigned m = __ballot_sync(0xffffffffu, pred);
            if (m) {
                if (first < 0) first = __shfl_sync(0xffffffffu, i, __ffs(m) - 1);
                if (pred) {
                    int rank = __popc(m & ((1u << lane) - 1u));
                    int slot = count + rank;
                    if (slot < NK) out[slot] = i;
                }
                count += __popc(m);
            }
        }
    }
    if (count < NK) {
        int fill = (count == 0) ? (NPTS - 1) : first;
        if (lane >= count) out[lane] = fill;
    }
}

// =====================================================================
// Kernel 2: fused layer1+layer2; x2 written FRAGMENT-MAJOR (uint4/tile).
// =====================================================================
#define B1_STR 152
#define B2_STR 72
#define SB12_B1HI 0
#define SB12_B1LO (SB12_B1HI + 64*B1_STR*2)    // 19456
#define SB12_B2HI (SB12_B1LO + 64*B1_STR*2)    // 38912
#define SB12_B2LO (SB12_B2HI + 128*B2_STR*2)   // 57344
#define SB12_SC1  (SB12_B2LO + 128*B2_STR*2)   // 75776
#define SB12_SH1  (SB12_SC1 + 64*4)
#define SB12_SC2  (SB12_SH1 + 64*4)
#define SB12_SH2  (SB12_SC2 + 128*4)
#define SB12_TOT  (SB12_SH2 + 128*4)           // 77312

__global__ __launch_bounds__(256, 2) void mlp12_mma_kernel(
    const float* __restrict__ points, const float* __restrict__ features,
    const float* __restrict__ refs)
{
    extern __shared__ char smc[];
    __nv_bfloat16* B1hi = (__nv_bfloat16*)(smc + SB12_B1HI);
    __nv_bfloat16* B1lo = (__nv_bfloat16*)(smc + SB12_B1LO);
    __nv_bfloat16* B2hi = (__nv_bfloat16*)(smc + SB12_B2HI);
    __nv_bfloat16* B2lo = (__nv_bfloat16*)(smc + SB12_B2LO);
    float* sc1s = (float*)(smc + SB12_SC1);
    float* sh1s = (float*)(smc + SB12_SH1);
    float* sc2s = (float*)(smc + SB12_SC2);
    float* sh2s = (float*)(smc + SB12_SH2);

    int t = threadIdx.x;
    int lane = t & 31, w = t >> 5;
    int g = blockIdx.x;
    int ref0 = g * 4;
    int b = ref0 >> 10;

    {
        uint4* d1h = (uint4*)B1hi; const uint4* s1h = (const uint4*)g_b1hi;
        uint4* d1l = (uint4*)B1lo; const uint4* s1l = (const uint4*)g_b1lo;
        for (int e = t; e < 1216; e += 256) { d1h[e] = s1h[e]; d1l[e] = s1l[e]; }
        uint4* d2h = (uint4*)B2hi; const uint4* s2h = (const uint4*)g_b2hi;
        uint4* d2l = (uint4*)B2lo; const uint4* s2l = (const uint4*)g_b2lo;
        for (int e = t; e < 1152; e += 256) { d2h[e] = s2h[e]; d2l[e] = s2l[e]; }
        if (t < 64) { sc1s[t] = g_sc1[t]; sh1s[t] = g_sh1[t]; }
        if (t < 128) { sc2s[t] = g_sc2[t]; sh2s[t] = g_sh2[t]; }
    }
    __syncthreads();

    int rl = lane >> 2;           // 0..7
    int cl = (lane & 3) * 2;      // 0,2,4,6

    int q = w >> 1;
    int ridx = ref0 + q;
    int rA = 16 * w + rl;
    int rB = rA + 8;
    int pidA = g_idx[ridx * NK + (rA & 31)];
    int pidB = g_idx[ridx * NK + (rB & 31)];
    const float* fA = features + ((size_t)b * NPTS + pidA) * 128;
    const float* fB = features + ((size_t)b * NPTS + pidB) * 128;
    float pA0, pA1, pA2, pB0, pB1, pB2;
    {
        const float* pa = points + ((size_t)b * NPTS + pidA) * 3;
        const float* pb = points + ((size_t)b * NPTS + pidB) * 3;
        const float* rr = refs + (size_t)ridx * 3;
        float r0v = rr[0], r1v = rr[1], r2v = rr[2];
        pA0 = (pa[0] - r0v) * 5.0f; pA1 = (pa[1] - r1v) * 5.0f; pA2 = (pa[2] - r2v) * 5.0f;
        pB0 = (pb[0] - r0v) * 5.0f; pB1 = (pb[1] - r1v) * 5.0f; pB2 = (pb[2] - r2v) * 5.0f;
    }

    float d1[8][4];
    #pragma unroll
    for (int ni = 0; ni < 8; ni++)
        #pragma unroll
        for (int e = 0; e < 4; e++) d1[ni][e] = 0.0f;

    #pragma unroll
    for (int ks = 0; ks < 9; ks++) {
        int c = 16 * ks + cl;
        float vA0, vA1, vA8, vA9, vB0v, vB1v, vB8, vB9;
        if (ks == 0) {
            if (cl == 0)      { vA0 = pA0;      vA1 = pA1;      vB0v = pB0;      vB1v = pB1; }
            else if (cl == 2) { vA0 = pA2;      vA1 = fA[0];    vB0v = pB2;      vB1v = fB[0]; }
            else              { vA0 = fA[cl-3]; vA1 = fA[cl-2]; vB0v = fB[cl-3]; vB1v = fB[cl-2]; }
            vA8 = fA[cl + 5]; vA9 = fA[cl + 6];
            vB8 = fB[cl + 5]; vB9 = fB[cl + 6];
        } else if (ks == 8) {
            if (cl == 0)      { vA0 = fA[125]; vA1 = fA[126]; vB0v = fB[125]; vB1v = fB[126]; }
            else if (cl == 2) { vA0 = fA[127]; vA1 = 0.0f;    vB0v = fB[127]; vB1v = 0.0f; }
            else              { vA0 = 0.0f;    vA1 = 0.0f;    vB0v = 0.0f;    vB1v = 0.0f; }
            vA8 = 0.0f; vA9 = 0.0f; vB8 = 0.0f; vB9 = 0.0f;
        } else {
            vA0 = fA[c - 3]; vA1 = fA[c - 2]; vA8 = fA[c + 5]; vA9 = fA[c + 6];
            vB0v = fB[c - 3]; vB1v = fB[c - 2]; vB8 = fB[c + 5]; vB9 = fB[c + 6];
        }
        uint32_t ahi[4], alo[4];
        pack_hl2(vA0, vA1, ahi[0], alo[0]);
        pack_hl2(vB0v, vB1v, ahi[1], alo[1]);
        pack_hl2(vA8, vA9, ahi[2], alo[2]);
        pack_hl2(vB8, vB9, ahi[3], alo[3]);

        int k0 = 16 * ks;
        #pragma unroll
        for (int ni = 0; ni < 8; ni++) {
            int n = ni * 8 + rl, k = k0 + cl;
            uint32_t bh[2], bl[2];
            bh[0] = *(const uint32_t*)&B1hi[n * B1_STR + k];
            bh[1] = *(const uint32_t*)&B1hi[n * B1_STR + k + 8];
            bl[0] = *(const uint32_t*)&B1lo[n * B1_STR + k];
            bl[1] = *(const uint32_t*)&B1lo[n * B1_STR + k + 8];
            mma_bf16(d1[ni], ahi, bh);
            mma_bf16(d1[ni], ahi, bl);
            mma_bf16(d1[ni], alo, bh);
        }
    }

    uint32_t a2hi[4][4], a2lo[4][4];
    #pragma unroll
    for (int kb = 0; kb < 4; kb++) {
        int colL = 16 * kb + cl;
        int colR = colL + 8;
        float sL0 = sc1s[colL], hL0 = sh1s[colL], sL1 = sc1s[colL + 1], hL1 = sh1s[colL + 1];
        float sR0 = sc1s[colR], hR0 = sh1s[colR], sR1 = sc1s[colR + 1], hR1 = sh1s[colR + 1];
        float y0 = fmaxf(fmaf(d1[2 * kb][0], sL0, hL0), 0.0f);
        float y1 = fmaxf(fmaf(d1[2 * kb][1], sL1, hL1), 0.0f);
        float y2 = fmaxf(fmaf(d1[2 * kb][2], sL0, hL0), 0.0f);
        float y3 = fmaxf(fmaf(d1[2 * kb][3], sL1, hL1), 0.0f);
        float u0 = fmaxf(fmaf(d1[2 * kb + 1][0], sR0, hR0), 0.0f);
        float u1 = fmaxf(fmaf(d1[2 * kb + 1][1], sR1, hR1), 0.0f);
        float u2 = fmaxf(fmaf(d1[2 * kb + 1][2], sR0, hR0), 0.0f);
        float u3 = fmaxf(fmaf(d1[2 * kb + 1][3], sR1, hR1), 0.0f);
        pack_hl2(y0, y1, a2hi[kb][0], a2lo[kb][0]);
        pack_hl2(y2, y3, a2hi[kb][1], a2lo[kb][1]);
        pack_hl2(u0, u1, a2hi[kb][2], a2lo[kb][2]);
        pack_hl2(u2, u3, a2hi[kb][3], a2lo[kb][3]);
    }

    #pragma unroll
    for (int h = 0; h < 2; h++) {
        float d2[8][4];
        #pragma unroll
        for (int ni = 0; ni < 8; ni++)
            #pragma unroll
            for (int e = 0; e < 4; e++) d2[ni][e] = 0.0f;

        #pragma unroll
        for (int ks = 0; ks < 4; ks++) {
            int k = 16 * ks + cl;
            #pragma unroll
            for (int ni = 0; ni < 8; ni++) {
                int n = 64 * h + ni * 8 + rl;
                uint32_t bh[2], bl[2];
                bh[0] = *(const uint32_t*)&B2hi[n * B2_STR + k];
                bh[1] = *(const uint32_t*)&B2hi[n * B2_STR + k + 8];
                bl[0] = *(const uint32_t*)&B2lo[n * B2_STR + k];
                bl[1] = *(const uint32_t*)&B2lo[n * B2_STR + k + 8];
                mma_bf16(d2[ni], a2hi[ks], bh);
                mma_bf16(d2[ni], a2hi[ks], bl);
                mma_bf16(d2[ni], a2lo[ks], bh);
            }
        }
        // epilogue: BN+ReLU -> fragment-major g_x2f (uint4 per tile per plane)
        #pragma unroll
        for (int kp = 0; kp < 4; kp++) {
            int ni0 = 2 * kp, ni1 = 2 * kp + 1;
            int col0 = 64 * h + ni0 * 8 + cl;
            int col1 = 64 * h + ni1 * 8 + cl;
            float s00 = sc2s[col0], h00 = sh2s[col0], s01 = sc2s[col0 + 1], h01 = sh2s[col0 + 1];
            float s10 = sc2s[col1], h10 = sh2s[col1], s11 = sc2s[col1 + 1], h11 = sh2s[col1 + 1];
            // reg0: row rA (rl), k=cl (tile kk<8);  reg1: row rB;  reg2/3: kk>=8
            float yA0 = fmaxf(fmaf(d2[ni0][0], s00, h00), 0.0f);
            float yA1 = fmaxf(fmaf(d2[ni0][1], s01, h01), 0.0f);
            float yB0 = fmaxf(fmaf(d2[ni0][2], s00, h00), 0.0f);
            float yB1 = fmaxf(fmaf(d2[ni0][3], s01, h01), 0.0f);
            float zA0 = fmaxf(fmaf(d2[ni1][0], s10, h10), 0.0f);
            float zA1 = fmaxf(fmaf(d2[ni1][1], s11, h11), 0.0f);
            float zB0 = fmaxf(fmaf(d2[ni1][2], s10, h10), 0.0f);
            float zB1 = fmaxf(fmaf(d2[ni1][3], s11, h11), 0.0f);
            uint32_t r0h, r0l, r1h, r1l, r2h, r2l, r3h, r3l;
            pack_hl2(yA0, yA1, r0h, r0l);
            pack_hl2(yB0, yB1, r1h, r1l);
            pack_hl2(zA0, zA1, r2h, r2l);
            pack_hl2(zB0, zB1, r3h, r3l);
            int ks_t = 4 * h + kp;
            size_t base = ((((size_t)g * 8 + w) * 8) + ks_t) * 128 + lane * 4;
            *(uint4*)&g_x2fhi[base] = make_uint4(r0h, r1h, r2h, r3h);
            *(uint4*)&g_x2flo[base] = make_uint4(r0l, r1l, r2l, r3l);
        }
    }
}

// =====================================================================
// Kernel 3: layer3 — A fragments via single LDG.128 from fragment-major
// global; B fragments via ldmatrix.x4. 12 L1 ops per k-step (was 48).
// =====================================================================
#define BF_STRIDE 136
#define S3B_BHI 0
#define S3B_BLO (S3B_BHI + 128*BF_STRIDE*2)    // 34816
#define S3B_SC  (S3B_BLO + 128*BF_STRIDE*2)    // 69632
#define S3B_SH  (S3B_SC + 128*4)               // 70144
#define S3B_TOTAL (S3B_SH + 128*4)             // 70656

__global__ __launch_bounds__(256, 2) void mlp3_mma_kernel(float* __restrict__ out)
{
    extern __shared__ char smc[];
    __nv_bfloat16* Bhi = (__nv_bfloat16*)(smc + S3B_BHI);
    __nv_bfloat16* Blo = (__nv_bfloat16*)(smc + S3B_BLO);
    float* scs = (float*)(smc + S3B_SC);
    float* shs = (float*)(smc + S3B_SH);

    int t = threadIdx.x;
    int lane = t & 31, wid = t >> 5;
    int g = blockIdx.x;
    int colbase = blockIdx.y * 128;

    if (t < 128) {
        scs[t] = g_sc3[colbase + t];
        shs[t] = g_sh3[colbase + t];
    }
    {
        const uint4* sh4 = (const uint4*)g_w3hi + colbase * 17;
        const uint4* sl4 = (const uint4*)g_w3lo + colbase * 17;
        uint4* dh4 = (uint4*)Bhi;
        uint4* dl4 = (uint4*)Blo;
        for (int e = t; e < 128 * 17; e += 256) {
            dh4[e] = sh4[e];
            dl4[e] = sl4[e];
        }
    }
    __syncthreads();

    int c0 = (wid & 1) * 64;
    int q  = wid >> 1;

    float d[2][8][4];
    #pragma unroll
    for (int mi = 0; mi < 2; mi++)
        #pragma unroll
        for (int ni = 0; ni < 8; ni++)
            #pragma unroll
            for (int e = 0; e < 4; e++) d[mi][ni][e] = 0.0f;

    int rl = lane >> 2;
    int cl = (lane & 3) * 2;

    // A: fragment-major base for this warp's two mb tiles (mb = 2q + mi)
    const uint32_t* Afh = g_x2fhi + (size_t)g * 8192 + (size_t)(2 * q) * 1024 + lane * 4;
    const uint32_t* Afl = g_x2flo + (size_t)g * 8192 + (size_t)(2 * q) * 1024 + lane * 4;

    // B ldmatrix addresses (per np pair of ni tiles), k0 added in-loop
    uint32_t bhAddr[4], blAddr[4];
    {
        int group = lane >> 3, r = lane & 7;
        int koff = 8 * (group & 1);
        int nofs = 8 * (group >> 1) + r;
        #pragma unroll
        for (int np = 0; np < 4; np++) {
            int n = c0 + 16 * np + nofs;
            uint32_t off = (uint32_t)(n * BF_STRIDE + koff) * 2;
            bhAddr[np] = (uint32_t)__cvta_generic_to_shared(Bhi) + off;
            blAddr[np] = (uint32_t)__cvta_generic_to_shared(Blo) + off;
        }
    }

    for (int ks = 0; ks < 8; ks++) {
        // A fragments: one LDG.128 per (mi, plane)
        uint32_t ahi[2][4], alo[2][4];
        #pragma unroll
        for (int mi = 0; mi < 2; mi++) {
            uint4 vh = *(const uint4*)(Afh + (size_t)mi * 1024 + ks * 128);
            uint4 vl = *(const uint4*)(Afl + (size_t)mi * 1024 + ks * 128);
            ahi[mi][0] = vh.x; ahi[mi][1] = vh.y; ahi[mi][2] = vh.z; ahi[mi][3] = vh.w;
            alo[mi][0] = vl.x; alo[mi][1] = vl.y; alo[mi][2] = vl.z; alo[mi][3] = vl.w;
        }
        // B fragments: ldmatrix.x4 per np per plane
        uint32_t bhi[8][2], blo[8][2];
        uint32_t kbyte = (uint32_t)(ks * 16) * 2;
        #pragma unroll
        for (int np = 0; np < 4; np++) {
            uint32_t rh[4], rlv[4];
            ldsm_x4(rh, bhAddr[np] + kbyte);
            ldsm_x4(rlv, blAddr[np] + kbyte);
            bhi[2 * np][0] = rh[0]; bhi[2 * np][1] = rh[1];
            bhi[2 * np + 1][0] = rh[2]; bhi[2 * np + 1][1] = rh[3];
            blo[2 * np][0] = rlv[0]; blo[2 * np][1] = rlv[1];
            blo[2 * np + 1][0] = rlv[2]; blo[2 * np + 1][1] = rlv[3];
        }
        #pragma unroll
        for (int mi = 0; mi < 2; mi++)
            #pragma unroll
            for (int ni = 0; ni < 8; ni++) {
                mma_bf16(d[mi][ni], ahi[mi], bhi[ni]);
                mma_bf16(d[mi][ni], ahi[mi], blo[ni]);
                mma_bf16(d[mi][ni], alo[mi], bhi[ni]);
            }
    }

    #pragma unroll
    for (int ni = 0; ni < 8; ni++) {
        #pragma unroll
        for (int e = 0; e < 2; e++) {
            int col = c0 + ni * 8 + cl + e;
            float s = scs[col], h = shs[col];
            float mx = 0.0f;
            #pragma unroll
            for (int mi = 0; mi < 2; mi++) {
                mx = fmaxf(mx, fmaxf(fmaf(d[mi][ni][e],     s, h), 0.0f));
                mx = fmaxf(mx, fmaxf(fmaf(d[mi][ni][2 + e], s, h), 0.0f));
            }
            mx = fmaxf(mx, __shfl_xor_sync(0xffffffffu, mx, 4));
            mx = fmaxf(mx, __shfl_xor_sync(0xffffffffu, mx, 8));
            mx = fmaxf(mx, __shfl_xor_sync(0xffffffffu, mx, 16));
            if (lane < 4)
                out[((size_t)g * 4 + q) * 256 + colbase + col] = mx;
        }
    }
}

// =====================================================================
extern "C" void kernel_launch(void* const* d_in, const int* in_sizes, int n_in,
                              void* d_out, int out_size)
{
    const float* points   = (const float*)d_in[0];
    const float* features = (const float*)d_in[1];
    const float* refs     = (const float*)d_in[2];
    const float* W1 = (const float*)d_in[3];
    const float* g1 = (const float*)d_in[4];
    const float* b1 = (const float*)d_in[5];
    const float* m1 = (const float*)d_in[6];
    const float* v1 = (const float*)d_in[7];
    const float* W2 = (const float*)d_in[8];
    const float* g2 = (const float*)d_in[9];
    const float* b2 = (const float*)d_in[10];
    const float* m2 = (const float*)d_in[11];
    const float* v2 = (const float*)d_in[12];
    const float* W3 = (const float*)d_in[13];
    const float* g3 = (const float*)d_in[14];
    const float* b3 = (const float*)d_in[15];
    const float* m3 = (const float*)d_in[16];
    const float* v3 = (const float*)d_in[17];
    float* out = (float*)d_out;

    cudaFuncSetAttribute(mlp12_mma_kernel, cudaFuncAttributeMaxDynamicSharedMemorySize, SB12_TOT);
    cudaFuncSetAttribute(mlp3_mma_kernel,  cudaFuncAttributeMaxDynamicSharedMemorySize, S3B_TOTAL);

    prep_kernel<<<64, 256>>>(W1, W2, W3, g1, b1, m1, v1,
                             g2, b2, m2, v2, g3, b3, m3, v3);
    ball_query_kernel<<<NREF / 8, 256>>>(points, refs);
    mlp12_mma_kernel<<<NREF / 4, 256, SB12_TOT>>>(points, features, refs);
    mlp3_mma_kernel<<<dim3(NREF / 4, 2), 256, S3B_TOTAL>>>(out);
}

// round 16
// speedup vs baseline: 4.0804x; 1.0004x over previous
#include <cuda_runtime.h>
#include <cuda_bf16.h>
#include <math.h>
#include <stdint.h>

#define BATCH 4
#define NPTS 20000
#define NS 1024
#define NC 128
#define NK 32
#define NREF (BATCH * NS)   // 4096

// ---------------- scratch (static device globals; no allocations) ----------------
__device__ int   g_idx[NREF * NK];                                   // 512 KB
// x2 in FRAGMENT-MAJOR layout: [group g][mb 0..7][ks 0..7][lane 0..31][4 u32]
__device__ __align__(16) uint32_t g_x2fhi[(size_t)1024 * 8192];
__device__ __align__(16) uint32_t g_x2flo[(size_t)1024 * 8192];
// pre-converted weights (hi/lo bf16, n-major, padded/zero-filled K)
__device__ __align__(16) __nv_bfloat16 g_b1hi[64 * 152], g_b1lo[64 * 152];
__device__ __align__(16) __nv_bfloat16 g_b2hi[128 * 72], g_b2lo[128 * 72];
__device__ __align__(16) __nv_bfloat16 g_w3hi[256 * 136], g_w3lo[256 * 136];
__device__ float g_sc1[64], g_sh1[64], g_sc2[128], g_sh2[128], g_sc3[256], g_sh3[256];

__device__ __forceinline__ void split_bf(float v, __nv_bfloat16& h, __nv_bfloat16& l) {
    h = __float2bfloat16_rn(v);
    l = __float2bfloat16_rn(v - __bfloat162float(h));
}
__device__ __forceinline__ uint32_t pack_bf2(__nv_bfloat16 a, __nv_bfloat16 b) {
    uint16_t ua = *(uint16_t*)&a, ub = *(uint16_t*)&b;
    return (uint32_t)ua | ((uint32_t)ub << 16);
}
__device__ __forceinline__ void pack_hl2(float a, float b, uint32_t& hi, uint32_t& lo) {
    __nv_bfloat16 ha, la, hb, lb;
    split_bf(a, ha, la); split_bf(b, hb, lb);
    hi = pack_bf2(ha, hb); lo = pack_bf2(la, lb);
}
__device__ __forceinline__ void mma_bf16(float* d, const uint32_t* a, const uint32_t* b) {
    asm volatile(
        "mma.sync.aligned.m16n8k16.row.col.f32.bf16.bf16.f32 "
        "{%0,%1,%2,%3}, {%4,%5,%6,%7}, {%8,%9}, {%0,%1,%2,%3};"
        : "+f"(d[0]), "+f"(d[1]), "+f"(d[2]), "+f"(d[3])
        : "r"(a[0]), "r"(a[1]), "r"(a[2]), "r"(a[3]), "r"(b[0]), "r"(b[1]));
}
__device__ __forceinline__ void ldsm_x4(uint32_t* r, uint32_t addr) {
    asm volatile("ldmatrix.sync.aligned.m8n8.x4.shared.b16 {%0,%1,%2,%3}, [%4];"
                 : "=r"(r[0]), "=r"(r[1]), "=r"(r[2]), "=r"(r[3]) : "r"(addr));
}

// =====================================================================
// Kernel 0: prep — convert weights + BN coeffs once per launch.
// =====================================================================
__global__ __launch_bounds__(256) void prep_kernel(
    const float* __restrict__ W1, const float* __restrict__ W2, const float* __restrict__ W3,
    const float* __restrict__ g1, const float* __restrict__ b1,
    const float* __restrict__ m1, const float* __restrict__ v1,
    const float* __restrict__ g2, const float* __restrict__ b2,
    const float* __restrict__ m2, const float* __restrict__ v2,
    const float* __restrict__ g3, const float* __restrict__ b3,
    const float* __restrict__ m3, const float* __restrict__ v3)
{
    int tid = blockIdx.x * 256 + threadIdx.x;
    int stride = gridDim.x * 256;
    for (int i = tid; i < 64 * 152; i += stride) {
        int n = i / 152, k = i - n * 152;
        float wv = (k < 131) ? W1[k * 64 + n] : 0.0f;
        __nv_bfloat16 h, l; split_bf(wv, h, l);
        g_b1hi[i] = h; g_b1lo[i] = l;
    }
    for (int i = tid; i < 128 * 72; i += stride) {
        int n = i / 72, k = i - n * 72;
        float wv = (k < 64) ? W2[k * 128 + n] : 0.0f;
        __nv_bfloat16 h, l; split_bf(wv, h, l);
        g_b2hi[i] = h; g_b2lo[i] = l;
    }
    for (int i = tid; i < 256 * 136; i += stride) {
        int n = i / 136, k = i - n * 136;
        float wv = (k < 128) ? W3[k * 256 + n] : 0.0f;
        __nv_bfloat16 h, l; split_bf(wv, h, l);
        g_w3hi[i] = h; g_w3lo[i] = l;
    }
    if (tid < 64) {
        float s = g1[tid] * rsqrtf(v1[tid] + 1e-5f);
        g_sc1[tid] = s; g_sh1[tid] = b1[tid] - m1[tid] * s;
    } else if (tid < 192) {
        int j = tid - 64;
        float s = g2[j] * rsqrtf(v2[j] + 1e-5f);
        g_sc2[j] = s; g_sh2[j] = b2[j] - m2[j] * s;
    } else if (tid < 448) {
        int j = tid - 192;
        float s = g3[j] * rsqrtf(v3[j] + 1e-5f);
        g_sc3[j] = s; g_sh3[j] = b3[j] - m3[j] * s;
    }
}

// =====================================================================
// Kernel 1: ball query — 256 points per iteration (8 batched loads).
// =====================================================================
__global__ __launch_bounds__(256) void ball_query_kernel(
    const float* __restrict__ points, const float* __restrict__ refs)
{
    int warp = (blockIdx.x * 256 + threadIdx.x) >> 5;
    int lane = threadIdx.x & 31;
    if (warp >= NREF) return;
    int b = warp >> 10;
    const float* rp = refs + (size_t)warp * 3;
    float rx = rp[0], ry = rp[1], rz = rp[2];
    float rr2 = rx * rx + ry * ry + rz * rz;
    const float R2 = 0.2f * 0.2f;
    int* out = g_idx + warp * NK;
    const float* pbase = points + (size_t)b * NPTS * 3;

    int count = 0;
    int first = -1;
    for (int base = 0; base < NPTS && count < NK; base += 256) {
        float px[8], py[8], pz[8];
        #pragma unroll
        for (int j = 0; j < 8; j++) {
            int i = base + j * 32 + lane;
            bool valid = (i < NPTS);
            int ii = valid ? i : 0;
            px[j] = pbase[ii * 3 + 0];
            py[j] = pbase[ii * 3 + 1];
            pz[j] = pbase[ii * 3 + 2];
            if (!valid) { px[j] = 1e9f; }
        }
        #pragma unroll
        for (int j = 0; j < 8; j++) {
            int i = base + j * 32 + lane;
            float pp2 = px[j] * px[j] + py[j] * py[j] + pz[j] * pz[j];
            float dot = rx * px[j] + ry * py[j] + rz * pz[j];
            float d2 = rr2 + pp2 - 2.0f * dot;
            bool pred = d2 < R2;
            unsigned m = __ballot_sync(0xffffffffu, pred);
            if (m) {
                if (first < 0) first = __shfl_sync(0xffffffffu, i, __ffs(m) - 1);
                if (pred) {
                    int rank = __popc(m & ((1u << lane) - 1u));
                    int slot = count + rank;
                    if (slot < NK) out[slot] = i;
                }
                count += __popc(m);
            }
        }
    }
    if (count < NK) {
        int fill = (count == 0) ? (NPTS - 1) : first;
        if (lane >= count) out[lane] = fill;
    }
}

// =====================================================================
// Kernel 2: fused layer1+layer2; pass-reordered MMAs (no same-acc chains).
// =====================================================================
#define B1_STR 152
#define B2_STR 72
#define SB12_B1HI 0
#define SB12_B1LO (SB12_B1HI + 64*B1_STR*2)    // 19456
#define SB12_B2HI (SB12_B1LO + 64*B1_STR*2)    // 38912
#define SB12_B2LO (SB12_B2HI + 128*B2_STR*2)   // 57344
#define SB12_SC1  (SB12_B2LO + 128*B2_STR*2)   // 75776
#define SB12_SH1  (SB12_SC1 + 64*4)
#define SB12_SC2  (SB12_SH1 + 64*4)
#define SB12_SH2  (SB12_SC2 + 128*4)
#define SB12_TOT  (SB12_SH2 + 128*4)           // 77312

__global__ __launch_bounds__(256, 2) void mlp12_mma_kernel(
    const float* __restrict__ points, const float* __restrict__ features,
    const float* __restrict__ refs)
{
    extern __shared__ char smc[];
    __nv_bfloat16* B1hi = (__nv_bfloat16*)(smc + SB12_B1HI);
    __nv_bfloat16* B1lo = (__nv_bfloat16*)(smc + SB12_B1LO);
    __nv_bfloat16* B2hi = (__nv_bfloat16*)(smc + SB12_B2HI);
    __nv_bfloat16* B2lo = (__nv_bfloat16*)(smc + SB12_B2LO);
    float* sc1s = (float*)(smc + SB12_SC1);
    float* sh1s = (float*)(smc + SB12_SH1);
    float* sc2s = (float*)(smc + SB12_SC2);
    float* sh2s = (float*)(smc + SB12_SH2);

    int t = threadIdx.x;
    int lane = t & 31, w = t >> 5;
    int g = blockIdx.x;
    int ref0 = g * 4;
    int b = ref0 >> 10;

    {
        uint4* d1h = (uint4*)B1hi; const uint4* s1h = (const uint4*)g_b1hi;
        uint4* d1l = (uint4*)B1lo; const uint4* s1l = (const uint4*)g_b1lo;
        for (int e = t; e < 1216; e += 256) { d1h[e] = s1h[e]; d1l[e] = s1l[e]; }
        uint4* d2h = (uint4*)B2hi; const uint4* s2h = (const uint4*)g_b2hi;
        uint4* d2l = (uint4*)B2lo; const uint4* s2l = (const uint4*)g_b2lo;
        for (int e = t; e < 1152; e += 256) { d2h[e] = s2h[e]; d2l[e] = s2l[e]; }
        if (t < 64) { sc1s[t] = g_sc1[t]; sh1s[t] = g_sh1[t]; }
        if (t < 128) { sc2s[t] = g_sc2[t]; sh2s[t] = g_sh2[t]; }
    }
    __syncthreads();

    int rl = lane >> 2;           // 0..7
    int cl = (lane & 3) * 2;      // 0,2,4,6

    int q = w >> 1;
    int ridx = ref0 + q;
    int rA = 16 * w + rl;
    int rB = rA + 8;
    int pidA = g_idx[ridx * NK + (rA & 31)];
    int pidB = g_idx[ridx * NK + (rB & 31)];
    const float* fA = features + ((size_t)b * NPTS + pidA) * 128;
    const float* fB = features + ((size_t)b * NPTS + pidB) * 128;
    float pA0, pA1, pA2, pB0, pB1, pB2;
    {
        const float* pa = points + ((size_t)b * NPTS + pidA) * 3;
        const float* pb = points + ((size_t)b * NPTS + pidB) * 3;
        const float* rr = refs + (size_t)ridx * 3;
        float r0v = rr[0], r1v = rr[1], r2v = rr[2];
        pA0 = (pa[0] - r0v) * 5.0f; pA1 = (pa[1] - r1v) * 5.0f; pA2 = (pa[2] - r2v) * 5.0f;
        pB0 = (pb[0] - r0v) * 5.0f; pB1 = (pb[1] - r1v) * 5.0f; pB2 = (pb[2] - r2v) * 5.0f;
    }

    float d1[8][4];
    #pragma unroll
    for (int ni = 0; ni < 8; ni++)
        #pragma unroll
        for (int e = 0; e < 4; e++) d1[ni][e] = 0.0f;

    #pragma unroll
    for (int ks = 0; ks < 9; ks++) {
        int c = 16 * ks + cl;
        float vA0, vA1, vA8, vA9, vB0v, vB1v, vB8, vB9;
        if (ks == 0) {
            if (cl == 0)      { vA0 = pA0;      vA1 = pA1;      vB0v = pB0;      vB1v = pB1; }
            else if (cl == 2) { vA0 = pA2;      vA1 = fA[0];    vB0v = pB2;      vB1v = fB[0]; }
            else              { vA0 = fA[cl-3]; vA1 = fA[cl-2]; vB0v = fB[cl-3]; vB1v = fB[cl-2]; }
            vA8 = fA[cl + 5]; vA9 = fA[cl + 6];
            vB8 = fB[cl + 5]; vB9 = fB[cl + 6];
        } else if (ks == 8) {
            if (cl == 0)      { vA0 = fA[125]; vA1 = fA[126]; vB0v = fB[125]; vB1v = fB[126]; }
            else if (cl == 2) { vA0 = fA[127]; vA1 = 0.0f;    vB0v = fB[127]; vB1v = 0.0f; }
            else              { vA0 = 0.0f;    vA1 = 0.0f;    vB0v = 0.0f;    vB1v = 0.0f; }
            vA8 = 0.0f; vA9 = 0.0f; vB8 = 0.0f; vB9 = 0.0f;
        } else {
            vA0 = fA[c - 3]; vA1 = fA[c - 2]; vA8 = fA[c + 5]; vA9 = fA[c + 6];
            vB0v = fB[c - 3]; vB1v = fB[c - 2]; vB8 = fB[c + 5]; vB9 = fB[c + 6];
        }
        uint32_t ahi[4], alo[4];
        pack_hl2(vA0, vA1, ahi[0], alo[0]);
        pack_hl2(vB0v, vB1v, ahi[1], alo[1]);
        pack_hl2(vA8, vA9, ahi[2], alo[2]);
        pack_hl2(vB8, vB9, ahi[3], alo[3]);

        int k0 = 16 * ks;
        uint32_t bh[8][2], bl[8][2];
        #pragma unroll
        for (int ni = 0; ni < 8; ni++) {
            int n = ni * 8 + rl, k = k0 + cl;
            bh[ni][0] = *(const uint32_t*)&B1hi[n * B1_STR + k];
            bh[ni][1] = *(const uint32_t*)&B1hi[n * B1_STR + k + 8];
            bl[ni][0] = *(const uint32_t*)&B1lo[n * B1_STR + k];
            bl[ni][1] = *(const uint32_t*)&B1lo[n * B1_STR + k + 8];
        }
        #pragma unroll
        for (int ni = 0; ni < 8; ni++) mma_bf16(d1[ni], ahi, bh[ni]);
        #pragma unroll
        for (int ni = 0; ni < 8; ni++) mma_bf16(d1[ni], ahi, bl[ni]);
        #pragma unroll
        for (int ni = 0; ni < 8; ni++) mma_bf16(d1[ni], alo, bh[ni]);
    }

    uint32_t a2hi[4][4], a2lo[4][4];
    #pragma unroll
    for (int kb = 0; kb < 4; kb++) {
        int colL = 16 * kb + cl;
        int colR = colL + 8;
        float sL0 = sc1s[colL], hL0 = sh1s[colL], sL1 = sc1s[colL + 1], hL1 = sh1s[colL + 1];
        float sR0 = sc1s[colR], hR0 = sh1s[colR], sR1 = sc1s[colR + 1], hR1 = sh1s[colR + 1];
        float y0 = fmaxf(fmaf(d1[2 * kb][0], sL0, hL0), 0.0f);
        float y1 = fmaxf(fmaf(d1[2 * kb][1], sL1, hL1), 0.0f);
        float y2 = fmaxf(fmaf(d1[2 * kb][2], sL0, hL0), 0.0f);
        float y3 = fmaxf(fmaf(d1[2 * kb][3], sL1, hL1), 0.0f);
        float u0 = fmaxf(fmaf(d1[2 * kb + 1][0], sR0, hR0), 0.0f);
        float u1 = fmaxf(fmaf(d1[2 * kb + 1][1], sR1, hR1), 0.0f);
        float u2 = fmaxf(fmaf(d1[2 * kb + 1][2], sR0, hR0), 0.0f);
        float u3 = fmaxf(fmaf(d1[2 * kb + 1][3], sR1, hR1), 0.0f);
        pack_hl2(y0, y1, a2hi[kb][0], a2lo[kb][0]);
        pack_hl2(y2, y3, a2hi[kb][1], a2lo[kb][1]);
        pack_hl2(u0, u1, a2hi[kb][2], a2lo[kb][2]);
        pack_hl2(u2, u3, a2hi[kb][3], a2lo[kb][3]);
    }

    #pragma unroll
    for (int h = 0; h < 2; h++) {
        float d2[8][4];
        #pragma unroll
        for (int ni = 0; ni < 8; ni++)
            #pragma unroll
            for (int e = 0; e < 4; e++) d2[ni][e] = 0.0f;

        #pragma unroll
        for (int ks = 0; ks < 4; ks++) {
            int k = 16 * ks + cl;
            uint32_t bh[8][2], bl[8][2];
            #pragma unroll
            for (int ni = 0; ni < 8; ni++) {
                int n = 64 * h + ni * 8 + rl;
                bh[ni][0] = *(const uint32_t*)&B2hi[n * B2_STR + k];
                bh[ni][1] = *(const uint32_t*)&B2hi[n * B2_STR + k + 8];
                bl[ni][0] = *(const uint32_t*)&B2lo[n * B2_STR + k];
                bl[ni][1] = *(const uint32_t*)&B2lo[n * B2_STR + k + 8];
            }
            #pragma unroll
            for (int ni = 0; ni < 8; ni++) mma_bf16(d2[ni], a2hi[ks], bh[ni]);
            #pragma unroll
            for (int ni = 0; ni < 8; ni++) mma_bf16(d2[ni], a2hi[ks], bl[ni]);
            #pragma unroll
            for (int ni = 0; ni < 8; ni++) mma_bf16(d2[ni], a2lo[ks], bh[ni]);
        }
        // epilogue: BN+ReLU -> fragment-major g_x2f (uint4 per tile per plane)
        #pragma unroll
        for (int kp = 0; kp < 4; kp++) {
            int ni0 = 2 * kp, ni1 = 2 * kp + 1;
            int col0 = 64 * h + ni0 * 8 + cl;
            int col1 = 64 * h + ni1 * 8 + cl;
            float s00 = sc2s[col0], h00 = sh2s[col0], s01 = sc2s[col0 + 1], h01 = sh2s[col0 + 1];
            float s10 = sc2s[col1], h10 = sh2s[col1], s11 = sc2s[col1 + 1], h11 = sh2s[col1 + 1];
            float yA0 = fmaxf(fmaf(d2[ni0][0], s00, h00), 0.0f);
            float yA1 = fmaxf(fmaf(d2[ni0][1], s01, h01), 0.0f);
            float yB0 = fmaxf(fmaf(d2[ni0][2], s00, h00), 0.0f);
            float yB1 = fmaxf(fmaf(d2[ni0][3], s01, h01), 0.0f);
            float zA0 = fmaxf(fmaf(d2[ni1][0], s10, h10), 0.0f);
            float zA1 = fmaxf(fmaf(d2[ni1][1], s11, h11), 0.0f);
            float zB0 = fmaxf(fmaf(d2[ni1][2], s10, h10), 0.0f);
            float zB1 = fmaxf(fmaf(d2[ni1][3], s11, h11), 0.0f);
            uint32_t r0h, r0l, r1h, r1l, r2h, r2l, r3h, r3l;
            pack_hl2(yA0, yA1, r0h, r0l);
            pack_hl2(yB0, yB1, r1h, r1l);
            pack_hl2(zA0, zA1, r2h, r2l);
            pack_hl2(zB0, zB1, r3h, r3l);
            int ks_t = 4 * h + kp;
            size_t base = ((((size_t)g * 8 + w) * 8) + ks_t) * 128 + lane * 4;
            *(uint4*)&g_x2fhi[base] = make_uint4(r0h, r1h, r2h, r3h);
            *(uint4*)&g_x2flo[base] = make_uint4(r0l, r1l, r2l, r3l);
        }
    }
}

// =====================================================================
// Kernel 3: layer3 — A via LDG.128 fragment-major, B via ldmatrix.x4,
// pass-reordered MMAs.
// =====================================================================
#define BF_STRIDE 136
#define S3B_BHI 0
#define S3B_BLO (S3B_BHI + 128*BF_STRIDE*2)    // 34816
#define S3B_SC  (S3B_BLO + 128*BF_STRIDE*2)    // 69632
#define S3B_SH  (S3B_SC + 128*4)               // 70144
#define S3B_TOTAL (S3B_SH + 128*4)             // 70656

__global__ __launch_bounds__(256, 2) void mlp3_mma_kernel(float* __restrict__ out)
{
    extern __shared__ char smc[];
    __nv_bfloat16* Bhi = (__nv_bfloat16*)(smc + S3B_BHI);
    __nv_bfloat16* Blo = (__nv_bfloat16*)(smc + S3B_BLO);
    float* scs = (float*)(smc + S3B_SC);
    float* shs = (float*)(smc + S3B_SH);

    int t = threadIdx.x;
    int lane = t & 31, wid = t >> 5;
    int g = blockIdx.x;
    int colbase = blockIdx.y * 128;

    if (t < 128) {
        scs[t] = g_sc3[colbase + t];
        shs[t] = g_sh3[colbase + t];
    }
    {
        const uint4* sh4 = (const uint4*)g_w3hi + colbase * 17;
        const uint4* sl4 = (const uint4*)g_w3lo + colbase * 17;
        uint4* dh4 = (uint4*)Bhi;
        uint4* dl4 = (uint4*)Blo;
        for (int e = t; e < 128 * 17; e += 256) {
            dh4[e] = sh4[e];
            dl4[e] = sl4[e];
        }
    }
    __syncthreads();

    int c0 = (wid & 1) * 64;
    int q  = wid >> 1;

    float d[2][8][4];
    #pragma unroll
    for (int mi = 0; mi < 2; mi++)
        #pragma unroll
        for (int ni = 0; ni < 8; ni++)
            #pragma unroll
            for (int e = 0; e < 4; e++) d[mi][ni][e] = 0.0f;

    int rl = lane >> 2;
    int cl = (lane & 3) * 2;

    const uint32_t* Afh = g_x2fhi + (size_t)g * 8192 + (size_t)(2 * q) * 1024 + lane * 4;
    const uint32_t* Afl = g_x2flo + (size_t)g * 8192 + (size_t)(2 * q) * 1024 + lane * 4;

    uint32_t bhAddr[4], blAddr[4];
    {
        int group = lane >> 3, r = lane & 7;
        int koff = 8 * (group & 1);
        int nofs = 8 * (group >> 1) + r;
        #pragma unroll
        for (int np = 0; np < 4; np++) {
            int n = c0 + 16 * np + nofs;
            uint32_t off = (uint32_t)(n * BF_STRIDE + koff) * 2;
            bhAddr[np] = (uint32_t)__cvta_generic_to_shared(Bhi) + off;
            blAddr[np] = (uint32_t)__cvta_generic_to_shared(Blo) + off;
        }
    }

    for (int ks = 0; ks < 8; ks++) {
        uint32_t ahi[2][4], alo[2][4];
        #pragma unroll
        for (int mi = 0; mi < 2; mi++) {
            uint4 vh = *(const uint4*)(Afh + (size_t)mi * 1024 + ks * 128);
            uint4 vl = *(const uint4*)(Afl + (size_t)mi * 1024 + ks * 128);
            ahi[mi][0] = vh.x; ahi[mi][1] = vh.y; ahi[mi][2] = vh.z; ahi[mi][3] = vh.w;
            alo[mi][0] = vl.x; alo[mi][1] = vl.y; alo[mi][2] = vl.z; alo[mi][3] = vl.w;
        }
        uint32_t bhi[8][2], blo[8][2];
        uint32_t kbyte = (uint32_t)(ks * 16) * 2;
        #pragma unroll
        for (int np = 0; np < 4; np++) {
            uint32_t rh[4], rlv[4];
            ldsm_x4(rh, bhAddr[np] + kbyte);
            ldsm_x4(rlv, blAddr[np] + kbyte);
            bhi[2 * np][0] = rh[0]; bhi[2 * np][1] = rh[1];
            bhi[2 * np + 1][0] = rh[2]; bhi[2 * np + 1][1] = rh[3];
            blo[2 * np][0] = rlv[0]; blo[2 * np][1] = rlv[1];
            blo[2 * np + 1][0] = rlv[2]; blo[2 * np + 1][1] = rlv[3];
        }
        // pass-reordered: 16 MMAs between reuses of any accumulator
        #pragma unroll
        for (int mi = 0; mi < 2; mi++)
            #pragma unroll
            for (int ni = 0; ni < 8; ni++) mma_bf16(d[mi][ni], ahi[mi], bhi[ni]);
        #pragma unroll
        for (int mi = 0; mi < 2; mi++)
            #pragma unroll
            for (int ni = 0; ni < 8; ni++) mma_bf16(d[mi][ni], ahi[mi], blo[ni]);
        #pragma unroll
        for (int mi = 0; mi < 2; mi++)
            #pragma unroll
            for (int ni = 0; ni < 8; ni++) mma_bf16(d[mi][ni], alo[mi], bhi[ni]);
    }

    #pragma unroll
    for (int ni = 0; ni < 8; ni++) {
        #pragma unroll
        for (int e = 0; e < 2; e++) {
            int col = c0 + ni * 8 + cl + e;
            float s = scs[col], h = shs[col];
            float mx = 0.0f;
            #pragma unroll
            for (int mi = 0; mi < 2; mi++) {
                mx = fmaxf(mx, fmaxf(fmaf(d[mi][ni][e],     s, h), 0.0f));
                mx = fmaxf(mx, fmaxf(fmaf(d[mi][ni][2 + e], s, h), 0.0f));
            }
            mx = fmaxf(mx, __shfl_xor_sync(0xffffffffu, mx, 4));
            mx = fmaxf(mx, __shfl_xor_sync(0xffffffffu, mx, 8));
            mx = fmaxf(mx, __shfl_xor_sync(0xffffffffu, mx, 16));
            if (lane < 4)
                out[((size_t)g * 4 + q) * 256 + colbase + col] = mx;
        }
    }
}

// =====================================================================
extern "C" void kernel_launch(void* const* d_in, const int* in_sizes, int n_in,
                              void* d_out, int out_size)
{
    const float* points   = (const float*)d_in[0];
    const float* features = (const float*)d_in[1];
    const float* refs     = (const float*)d_in[2];
    const float* W1 = (const float*)d_in[3];
    const float* g1 = (const float*)d_in[4];
    const float* b1 = (const float*)d_in[5];
    const float* m1 = (const float*)d_in[6];
    const float* v1 = (const float*)d_in[7];
    const float* W2 = (const float*)d_in[8];
    const float* g2 = (const float*)d_in[9];
    const float* b2 = (const float*)d_in[10];
    const float* m2 = (const float*)d_in[11];
    const float* v2 = (const float*)d_in[12];
    const float* W3 = (const float*)d_in[13];
    const float* g3 = (const float*)d_in[14];
    const float* b3 = (const float*)d_in[15];
    const float* m3 = (const float*)d_in[16];
    const float* v3 = (const float*)d_in[17];
    float* out = (float*)d_out;

    cudaFuncSetAttribute(mlp12_mma_kernel, cudaFuncAttributeMaxDynamicSharedMemorySize, SB12_TOT);
    cudaFuncSetAttribute(mlp3_mma_kernel,  cudaFuncAttributeMaxDynamicSharedMemorySize, S3B_TOTAL);

    prep_kernel<<<64, 256>>>(W1, W2, W3, g1, b1, m1, v1,
                             g2, b2, m2, v2, g3, b3, m3, v3);
    ball_query_kernel<<<NREF / 8, 256>>>(points, refs);
    mlp12_mma_kernel<<<NREF / 4, 256, SB12_TOT>>>(points, features, refs);
    mlp3_mma_kernel<<<dim3(NREF / 4, 2), 256, S3B_TOTAL>>>(out);
}